// round 3
// baseline (speedup 1.0000x reference)
#include <cuda_runtime.h>

#define NN 50000
#define DD 512
#define EE 150000

// Scratch (static device globals: no allocation anywhere). 16B-aligned for
// float4 loads/stores and red.global.add.v4.f32.
__device__ __align__(16) float g_bufA[(size_t)NN * DD];   // 102.4 MB (GEMM out)
__device__ __align__(16) float g_bufB[(size_t)NN * DD];   // 102.4 MB (agg out L1)
__device__ float g_deg[NN];
__device__ float g_dis[NN];
__device__ int   g_is64;   // 1 if edge_index is int64, 0 if int32

// ---------------------------------------------------------------------------
// Edge-index dtype detection: int64 values < 2^31 have all-zero odd words.
// Scans 128 odd words (bytes < 1024 — safe under both interpretations).
// ---------------------------------------------------------------------------
__global__ void detect_dtype_kernel(const unsigned int* __restrict__ w) {
    if (threadIdx.x == 0 && blockIdx.x == 0) {
        int is64 = 1;
        for (int i = 0; i < 128; i++)
            if (w[2 * i + 1] != 0u) { is64 = 0; break; }
        g_is64 = is64;
    }
}

__device__ __forceinline__ int load_idx(const void* __restrict__ ei, int pos) {
    if (g_is64) return (int)((const long long*)ei)[pos];
    return ((const int*)ei)[pos];
}

// ---------------------------------------------------------------------------
// Degree / normalization
// ---------------------------------------------------------------------------
__global__ void init_deg_kernel() {
    int i = blockIdx.x * blockDim.x + threadIdx.x;
    if (i < NN) g_deg[i] = 1.0f;   // self-loop contributes 1 to every node
}

__global__ void count_deg_kernel(const void* __restrict__ ei) {
    int e = blockIdx.x * blockDim.x + threadIdx.x;
    if (e < EE) {
        int d = load_idx(ei, EE + e);   // dst = edge_index[1][e]
        atomicAdd(&g_deg[d], 1.0f);
    }
}

__global__ void calc_dis_kernel() {
    int i = blockIdx.x * blockDim.x + threadIdx.x;
    if (i < NN) g_dis[i] = rsqrtf(g_deg[i]);   // deg >= 1 always
}

// ---------------------------------------------------------------------------
// SGEMM: g_bufA[M,512] = op(A)[M,512] @ B[512,512]
// A source: external pointer (layer 1) or g_bufB (layer 2, with relu)
// BM=128, BN=64, BK=16, 256 threads, 8x4 microtile
// ---------------------------------------------------------------------------
template <bool A_FROM_BUFB, bool RELU_A>
__global__ __launch_bounds__(256) void sgemm_kernel(
    const float* __restrict__ Aext, const float* __restrict__ B, int M)
{
    const float* __restrict__ A = A_FROM_BUFB ? (const float*)g_bufB : Aext;
    float* __restrict__ C = g_bufA;

    __shared__ float As[16][132];   // transposed [k][m], padded
    __shared__ float Bs[16][64];    // [k][n]

    const int bm = blockIdx.x * 128;
    const int bn = blockIdx.y * 64;
    const int tid = threadIdx.x;

    const int a_row  = tid >> 2;        // 0..63 (two rows: a_row, a_row+64)
    const int a_col4 = tid & 3;         // float4 index within 16 cols
    const int b_row  = tid >> 4;        // 0..15
    const int b_col4 = tid & 15;        // float4 index within 64 cols

    const int tr = (tid >> 4) * 8;      // microtile row offset 0..120
    const int tc = (tid & 15) * 4;      // microtile col offset 0..60

    float acc[8][4];
#pragma unroll
    for (int i = 0; i < 8; i++)
#pragma unroll
        for (int j = 0; j < 4; j++) acc[i][j] = 0.0f;

    for (int k0 = 0; k0 < 512; k0 += 16) {
#pragma unroll
        for (int r = 0; r < 2; r++) {
            int row = a_row + r * 64;
            int grow = bm + row;
            float4 v = make_float4(0.f, 0.f, 0.f, 0.f);
            if (grow < M)
                v = *(const float4*)&A[(size_t)grow * 512 + k0 + a_col4 * 4];
            if (RELU_A) {
                v.x = fmaxf(v.x, 0.f); v.y = fmaxf(v.y, 0.f);
                v.z = fmaxf(v.z, 0.f); v.w = fmaxf(v.w, 0.f);
            }
            As[a_col4 * 4 + 0][row] = v.x;
            As[a_col4 * 4 + 1][row] = v.y;
            As[a_col4 * 4 + 2][row] = v.z;
            As[a_col4 * 4 + 3][row] = v.w;
        }
        {
            float4 v = *(const float4*)&B[(size_t)(k0 + b_row) * 512 + bn + b_col4 * 4];
            *(float4*)&Bs[b_row][b_col4 * 4] = v;
        }
        __syncthreads();

#pragma unroll
        for (int k = 0; k < 16; k++) {
            float a[8], b[4];
#pragma unroll
            for (int i = 0; i < 8; i++) a[i] = As[k][tr + i];
#pragma unroll
            for (int j = 0; j < 4; j++) b[j] = Bs[k][tc + j];
#pragma unroll
            for (int i = 0; i < 8; i++)
#pragma unroll
                for (int j = 0; j < 4; j++) acc[i][j] = fmaf(a[i], b[j], acc[i][j]);
        }
        __syncthreads();
    }

#pragma unroll
    for (int i = 0; i < 8; i++) {
        int row = bm + tr + i;
        if (row < M) {
            float4 v = make_float4(acc[i][0], acc[i][1], acc[i][2], acc[i][3]);
            *(float4*)&C[(size_t)row * 512 + bn + tc] = v;
        }
    }
}

// ---------------------------------------------------------------------------
// Aggregation init: agg[i,:] = g_bufA[i,:] * dis[i]^2 (self-loop) + bias
// ---------------------------------------------------------------------------
template <bool TO_BUFB>
__global__ void init_agg_kernel(const float* __restrict__ bias,
                                float* __restrict__ agg_ext)
{
    float* __restrict__ agg = TO_BUFB ? (float*)g_bufB : agg_ext;
    const float* __restrict__ h = g_bufA;

    int idx = blockIdx.x * blockDim.x + threadIdx.x;   // float4 index
    const int total = NN * DD / 4;
    if (idx >= total) return;
    int row = idx / (DD / 4);
    int c4  = idx - row * (DD / 4);
    float w = g_dis[row];
    w = w * w;                                          // 1/deg
    float4 hv = ((const float4*)h)[idx];
    float4 bv = ((const float4*)bias)[c4];
    float4 o;
    o.x = fmaf(hv.x, w, bv.x);
    o.y = fmaf(hv.y, w, bv.y);
    o.z = fmaf(hv.z, w, bv.z);
    o.w = fmaf(hv.w, w, bv.w);
    ((float4*)agg)[idx] = o;
}

// ---------------------------------------------------------------------------
// Edge scatter: agg[dst,:] += dis[src]*dis[dst] * g_bufA[src,:]
// One warp per edge; vector RED (sm_90+)
// ---------------------------------------------------------------------------
template <bool TO_BUFB>
__global__ __launch_bounds__(256) void edge_scatter_kernel(
    const void* __restrict__ ei, float* __restrict__ agg_ext)
{
    float* __restrict__ agg = TO_BUFB ? (float*)g_bufB : agg_ext;
    const float* __restrict__ h = g_bufA;

    int warp = (blockIdx.x * blockDim.x + threadIdx.x) >> 5;
    int lane = threadIdx.x & 31;
    if (warp >= EE) return;
    int s = load_idx(ei, warp);
    int d = load_idx(ei, EE + warp);
    float w = g_dis[s] * g_dis[d];
    const float4* hr = (const float4*)(h + (size_t)s * DD);
    float* ar = agg + (size_t)d * DD;
#pragma unroll
    for (int i = 0; i < 4; i++) {
        int c4 = lane + i * 32;
        float4 v = hr[c4];
        float* p = ar + c4 * 4;
        asm volatile("red.global.add.v4.f32 [%0], {%1,%2,%3,%4};"
                     :: "l"(p), "f"(v.x * w), "f"(v.y * w),
                        "f"(v.z * w), "f"(v.w * w)
                     : "memory");
    }
}

// ---------------------------------------------------------------------------
// Launch (kernel launches ONLY — graph-capturable)
// ---------------------------------------------------------------------------
extern "C" void kernel_launch(void* const* d_in, const int* in_sizes, int n_in,
                              void* d_out, int out_size)
{
    const float* x  = (const float*)d_in[0];
    const void*  ei = d_in[1];                    // int32 or int64, detected on device
    const float* W1 = (const float*)d_in[2];
    const float* b1 = (const float*)d_in[3];
    const float* W2 = (const float*)d_in[4];
    const float* b2 = (const float*)d_in[5];
    float* out = (float*)d_out;

    detect_dtype_kernel<<<1, 32>>>((const unsigned int*)ei);

    // normalization
    init_deg_kernel<<<(NN + 255) / 256, 256>>>();
    count_deg_kernel<<<(EE + 255) / 256, 256>>>(ei);
    calc_dis_kernel<<<(NN + 255) / 256, 256>>>();

    dim3 gemm_grid((NN + 127) / 128, DD / 64);
    const int agg_blocks  = (NN * DD / 4 + 255) / 256;
    const int edge_blocks = (EE + 7) / 8;   // 8 warps per block, 1 warp/edge

    // Layer 1: g_bufA = x @ W1 ; g_bufB = Ahat*g_bufA + b1
    sgemm_kernel<false, false><<<gemm_grid, 256>>>(x, W1, NN);
    init_agg_kernel<true><<<agg_blocks, 256>>>(b1, nullptr);
    edge_scatter_kernel<true><<<edge_blocks, 256>>>(ei, nullptr);

    // Layer 2: g_bufA = relu(g_bufB) @ W2 ; out = Ahat*g_bufA + b2
    sgemm_kernel<true, true><<<gemm_grid, 256>>>(nullptr, W2, NN);
    init_agg_kernel<false><<<agg_blocks, 256>>>(b2, out);
    edge_scatter_kernel<false><<<edge_blocks, 256>>>(ei, out);
}

// round 7
// speedup vs baseline: 1.8574x; 1.8574x over previous
#include <cuda_runtime.h>
#include <cuda_bf16.h>
#include <cstdint>

#define NN 50000
#define DD 512
#define EE 150000

#define BM 128
#define BN 128
#define BK 32
#define SA 40          // smem row stride in bf16 elems (80B -> conflict-free ldmatrix)

// ---------------------------------------------------------------------------
// Device globals (no allocation anywhere)
// ---------------------------------------------------------------------------
__device__ __align__(16) float g_bufA[(size_t)NN * DD];   // GEMM output h
__device__ __align__(16) float g_bufB[(size_t)NN * DD];   // layer-1 aggregate
__device__ __align__(16) __nv_bfloat16 g_W1h[DD * DD], g_W1l[DD * DD];
__device__ __align__(16) __nv_bfloat16 g_W2h[DD * DD], g_W2l[DD * DD];
__device__ float g_deg[NN];
__device__ float g_dis[NN];
__device__ int   g_is64;

// ---------------------------------------------------------------------------
// PTX helpers (all legal on plain sm_103 target: ldmatrix/mma.sync are sm_80+)
// ---------------------------------------------------------------------------
__device__ __forceinline__ uint32_t smem_u32(const void* p) {
    uint32_t a;
    asm("{ .reg .u64 t; cvta.to.shared.u64 t, %1; cvt.u32.u64 %0, t; }"
        : "=r"(a) : "l"(p));
    return a;
}
#define LDM4(d, addr)                                                           \
    asm volatile("ldmatrix.sync.aligned.m8n8.x4.shared.b16 {%0,%1,%2,%3}, [%4];"\
        : "=r"((d)[0]), "=r"((d)[1]), "=r"((d)[2]), "=r"((d)[3]) : "r"(addr))
#define MMA(cc, aa, b0, b1)                                                     \
    asm volatile("mma.sync.aligned.m16n8k16.row.col.f32.bf16.bf16.f32 "         \
        "{%0,%1,%2,%3}, {%4,%5,%6,%7}, {%8,%9}, {%0,%1,%2,%3};"                 \
        : "+f"((cc)[0]), "+f"((cc)[1]), "+f"((cc)[2]), "+f"((cc)[3])            \
        : "r"((aa)[0]), "r"((aa)[1]), "r"((aa)[2]), "r"((aa)[3]),               \
          "r"(b0), "r"(b1))

__device__ __forceinline__ uint32_t pack_bf16(__nv_bfloat16 a, __nv_bfloat16 b) {
    __nv_bfloat162 t; t.x = a; t.y = b;           // x = low half
    return *reinterpret_cast<uint32_t*>(&t);
}

// ---------------------------------------------------------------------------
// Edge-index dtype detection (int64 values < 2^31 -> odd words all zero)
// ---------------------------------------------------------------------------
__global__ void detect_dtype_kernel(const unsigned int* __restrict__ w) {
    if (threadIdx.x == 0 && blockIdx.x == 0) {
        int is64 = 1;
        for (int i = 0; i < 128; i++)
            if (w[2 * i + 1] != 0u) { is64 = 0; break; }
        g_is64 = is64;
    }
}
__device__ __forceinline__ int load_idx(const void* __restrict__ ei, int pos) {
    if (g_is64) return (int)((const long long*)ei)[pos];
    return ((const int*)ei)[pos];
}

// ---------------------------------------------------------------------------
// Degree / normalization
// ---------------------------------------------------------------------------
__global__ void init_deg_kernel() {
    int i = blockIdx.x * blockDim.x + threadIdx.x;
    if (i < NN) g_deg[i] = 1.0f;
}
__global__ void count_deg_kernel(const void* __restrict__ ei) {
    int e = blockIdx.x * blockDim.x + threadIdx.x;
    if (e < EE) atomicAdd(&g_deg[load_idx(ei, EE + e)], 1.0f);
}
__global__ void calc_dis_kernel() {
    int i = blockIdx.x * blockDim.x + threadIdx.x;
    if (i < NN) g_dis[i] = rsqrtf(g_deg[i]);
}

// ---------------------------------------------------------------------------
// W transpose + bf16 hi/lo split: Wh[n][k] = bf16(W[k][n]), Wl = bf16(residual)
// ---------------------------------------------------------------------------
template <int LAYER>
__global__ void wsplit_kernel(const float* __restrict__ W) {
    __nv_bfloat16* __restrict__ Wh = (LAYER == 1) ? g_W1h : g_W2h;
    __nv_bfloat16* __restrict__ Wl = (LAYER == 1) ? g_W1l : g_W2l;
    __shared__ float t[32][33];
    int k0 = blockIdx.x * 32, n0 = blockIdx.y * 32;
    int tx = threadIdx.x, ty0 = threadIdx.y;
    for (int j = ty0; j < 32; j += 8)
        t[j][tx] = W[(size_t)(k0 + j) * DD + n0 + tx];
    __syncthreads();
    for (int j = ty0; j < 32; j += 8) {
        float a = t[tx][j];                        // = W[k0+tx][n0+j]
        __nv_bfloat16 h = __float2bfloat16(a);
        float lo = a - __bfloat162float(h);
        Wh[(size_t)(n0 + j) * DD + k0 + tx] = h;
        Wl[(size_t)(n0 + j) * DD + k0 + tx] = __float2bfloat16(lo);
    }
}

// ---------------------------------------------------------------------------
// bf16x3 tensor-core GEMM: g_bufA[M,512] = op(A)[M,512] @ W[512,512]
// 8 warps: warp grid 4(m) x 2(n); warp tile 32x64; mma m16n8k16
// ---------------------------------------------------------------------------
template <bool A_BUFB, bool RELU, int LAYER>
__global__ __launch_bounds__(256, 1) void gemm_bf16x3(
    const float* __restrict__ Aext, int M)
{
    const float* __restrict__ A = A_BUFB ? (const float*)g_bufB : Aext;
    const __nv_bfloat16* __restrict__ Wh = (LAYER == 1) ? g_W1h : g_W2h;
    const __nv_bfloat16* __restrict__ Wl = (LAYER == 1) ? g_W1l : g_W2l;
    float* __restrict__ C = g_bufA;

    __shared__ __align__(16) uint16_t Ash[BM * SA], Asl[BM * SA];
    __shared__ __align__(16) uint16_t Bsh[BN * SA], Bsl[BN * SA];

    const int tid = threadIdx.x, lane = tid & 31, wid = tid >> 5;
    const int wm = (wid & 3) * 32;       // warp m offset in tile
    const int wn = (wid >> 2) * 64;      // warp n offset in tile
    const int bm = blockIdx.y * BM;
    const int n0 = blockIdx.x * BN;

    float4 pa[4];
    uint4  pbh[2], pbl[2];

    // ---- prefetch tile (k0) into registers ----
    auto prefetch = [&](int k0) {
#pragma unroll
        for (int r = 0; r < 4; r++) {
            int idx = tid + 256 * r;
            int row = idx >> 3, c4 = idx & 7;
            int g = bm + row;
            float4 v = make_float4(0.f, 0.f, 0.f, 0.f);
            if (g < M) v = *(const float4*)&A[(size_t)g * DD + k0 + c4 * 4];
            pa[r] = v;
        }
#pragma unroll
        for (int r = 0; r < 2; r++) {
            int idx = tid + 256 * r;
            int row = idx >> 2, c = idx & 3;
            size_t g = (size_t)(n0 + row) * DD + k0 + c * 8;
            pbh[r] = *(const uint4*)&Wh[g];
            pbl[r] = *(const uint4*)&Wl[g];
        }
    };
    // ---- commit registers -> smem (with relu + hi/lo split for A) ----
    auto commit = [&]() {
#pragma unroll
        for (int r = 0; r < 4; r++) {
            int idx = tid + 256 * r;
            int row = idx >> 3, c4 = idx & 7;
            float4 v = pa[r];
            if (RELU) {
                v.x = fmaxf(v.x, 0.f); v.y = fmaxf(v.y, 0.f);
                v.z = fmaxf(v.z, 0.f); v.w = fmaxf(v.w, 0.f);
            }
            __nv_bfloat16 hx = __float2bfloat16(v.x);
            __nv_bfloat16 hy = __float2bfloat16(v.y);
            __nv_bfloat16 hz = __float2bfloat16(v.z);
            __nv_bfloat16 hw = __float2bfloat16(v.w);
            __nv_bfloat16 lx = __float2bfloat16(v.x - __bfloat162float(hx));
            __nv_bfloat16 ly = __float2bfloat16(v.y - __bfloat162float(hy));
            __nv_bfloat16 lz = __float2bfloat16(v.z - __bfloat162float(hz));
            __nv_bfloat16 lw = __float2bfloat16(v.w - __bfloat162float(hw));
            uint2 H = make_uint2(pack_bf16(hx, hy), pack_bf16(hz, hw));
            uint2 L = make_uint2(pack_bf16(lx, ly), pack_bf16(lz, lw));
            *(uint2*)&Ash[row * SA + c4 * 4] = H;
            *(uint2*)&Asl[row * SA + c4 * 4] = L;
        }
#pragma unroll
        for (int r = 0; r < 2; r++) {
            int idx = tid + 256 * r;
            int row = idx >> 2, c = idx & 3;
            *(uint4*)&Bsh[row * SA + c * 8] = pbh[r];
            *(uint4*)&Bsl[row * SA + c * 8] = pbl[r];
        }
    };

    const uint32_t aB  = smem_u32(Ash), aL = smem_u32(Asl);
    const uint32_t bB  = smem_u32(Bsh), bL = smem_u32(Bsl);

    float c[2][8][4];
#pragma unroll
    for (int i = 0; i < 2; i++)
#pragma unroll
        for (int j = 0; j < 8; j++)
#pragma unroll
            for (int q = 0; q < 4; q++) c[i][j][q] = 0.0f;

    prefetch(0);
    commit();
    __syncthreads();

    for (int it = 0; it < DD / BK; it++) {
        if (it < DD / BK - 1) prefetch((it + 1) * BK);   // LDGs fly during mma

#pragma unroll
        for (int ks = 0; ks < 2; ks++) {
            const int k0s = ks * 16;
            // A fragments: 2 m-tiles (16 rows), x4 ldmatrix each, hi+lo
            uint32_t ah[2][4], al[2][4];
#pragma unroll
            for (int mi = 0; mi < 2; mi++) {
                uint32_t off = (uint32_t)(((wm + mi * 16 + (lane & 15)) * SA
                                + k0s + 8 * (lane >> 4)) * 2);
                LDM4(ah[mi], aB + off);
                LDM4(al[mi], aL + off);
            }
            // B fragments: 8 n-tiles via 4 x4-ldmatrix (2 tiles each), hi+lo
            uint32_t bh[4][4], bl[4][4];
#pragma unroll
            for (int nj = 0; nj < 4; nj++) {
                uint32_t off = (uint32_t)(((wn + nj * 16 + (lane & 7)
                                + 8 * (lane >> 4)) * SA
                                + k0s + 8 * ((lane >> 3) & 1)) * 2);
                LDM4(bh[nj], bB + off);
                LDM4(bl[nj], bL + off);
            }
#pragma unroll
            for (int mi = 0; mi < 2; mi++)
#pragma unroll
                for (int nj = 0; nj < 4; nj++) {
                    MMA(c[mi][nj * 2],     ah[mi], bh[nj][0], bh[nj][1]);
                    MMA(c[mi][nj * 2],     ah[mi], bl[nj][0], bl[nj][1]);
                    MMA(c[mi][nj * 2],     al[mi], bh[nj][0], bh[nj][1]);
                    MMA(c[mi][nj * 2 + 1], ah[mi], bh[nj][2], bh[nj][3]);
                    MMA(c[mi][nj * 2 + 1], ah[mi], bl[nj][2], bl[nj][3]);
                    MMA(c[mi][nj * 2 + 1], al[mi], bh[nj][2], bh[nj][3]);
                }
        }
        __syncthreads();
        if (it < DD / BK - 1) {
            commit();
            __syncthreads();
        }
    }

    // Epilogue: standard m16n8 C fragment mapping
#pragma unroll
    for (int mi = 0; mi < 2; mi++) {
        int r0 = bm + wm + mi * 16 + (lane >> 2);
#pragma unroll
        for (int nj = 0; nj < 8; nj++) {
            int col = n0 + wn + nj * 8 + (lane & 3) * 2;
            if (r0 < M)
                *(float2*)&C[(size_t)r0 * DD + col] =
                    make_float2(c[mi][nj][0], c[mi][nj][1]);
            if (r0 + 8 < M)
                *(float2*)&C[(size_t)(r0 + 8) * DD + col] =
                    make_float2(c[mi][nj][2], c[mi][nj][3]);
        }
    }
}

// ---------------------------------------------------------------------------
// Aggregation: agg[i,:] = h[i,:]/deg[i] + bias ; then edge scatter-add
// ---------------------------------------------------------------------------
template <bool TO_BUFB>
__global__ void init_agg_kernel(const float* __restrict__ bias,
                                float* __restrict__ agg_ext)
{
    float* __restrict__ agg = TO_BUFB ? (float*)g_bufB : agg_ext;
    const float* __restrict__ h = g_bufA;
    int idx = blockIdx.x * blockDim.x + threadIdx.x;
    const int total = NN * DD / 4;
    if (idx >= total) return;
    int row = idx / (DD / 4);
    int c4  = idx - row * (DD / 4);
    float w = g_dis[row]; w = w * w;
    float4 hv = ((const float4*)h)[idx];
    float4 bv = ((const float4*)bias)[c4];
    float4 o;
    o.x = fmaf(hv.x, w, bv.x); o.y = fmaf(hv.y, w, bv.y);
    o.z = fmaf(hv.z, w, bv.z); o.w = fmaf(hv.w, w, bv.w);
    ((float4*)agg)[idx] = o;
}

template <bool TO_BUFB>
__global__ __launch_bounds__(256) void edge_scatter_kernel(
    const void* __restrict__ ei, float* __restrict__ agg_ext)
{
    float* __restrict__ agg = TO_BUFB ? (float*)g_bufB : agg_ext;
    const float* __restrict__ h = g_bufA;
    int warp = (blockIdx.x * blockDim.x + threadIdx.x) >> 5;
    int lane = threadIdx.x & 31;
    if (warp >= EE) return;
    int s = load_idx(ei, warp);
    int d = load_idx(ei, EE + warp);
    float w = g_dis[s] * g_dis[d];
    const float4* hr = (const float4*)(h + (size_t)s * DD);
    float* ar = agg + (size_t)d * DD;
#pragma unroll
    for (int i = 0; i < 4; i++) {
        int c4 = lane + i * 32;
        float4 v = hr[c4];
        float* p = ar + c4 * 4;
        asm volatile("red.global.add.v4.f32 [%0], {%1,%2,%3,%4};"
                     :: "l"(p), "f"(v.x * w), "f"(v.y * w),
                        "f"(v.z * w), "f"(v.w * w) : "memory");
    }
}

// ---------------------------------------------------------------------------
// Launch (kernel launches only — graph-capturable)
// ---------------------------------------------------------------------------
extern "C" void kernel_launch(void* const* d_in, const int* in_sizes, int n_in,
                              void* d_out, int out_size)
{
    const float* x  = (const float*)d_in[0];
    const void*  ei = d_in[1];
    const float* W1 = (const float*)d_in[2];
    const float* b1 = (const float*)d_in[3];
    const float* W2 = (const float*)d_in[4];
    const float* b2 = (const float*)d_in[5];
    float* out = (float*)d_out;

    detect_dtype_kernel<<<1, 32>>>((const unsigned int*)ei);
    init_deg_kernel<<<(NN + 255) / 256, 256>>>();
    count_deg_kernel<<<(EE + 255) / 256, 256>>>(ei);
    calc_dis_kernel<<<(NN + 255) / 256, 256>>>();

    dim3 wgrid(DD / 32, DD / 32);
    wsplit_kernel<1><<<wgrid, dim3(32, 8)>>>(W1);
    wsplit_kernel<2><<<wgrid, dim3(32, 8)>>>(W2);

    // grid.x = n-blocks (4) so CTAs sharing an A row-block run adjacently
    dim3 gemm_grid(DD / BN, (NN + BM - 1) / BM);   // (4, 391)
    const int agg_blocks  = (NN * DD / 4 + 255) / 256;
    const int edge_blocks = (EE + 7) / 8;

    gemm_bf16x3<false, false, 1><<<gemm_grid, 256>>>(x, NN);
    init_agg_kernel<true><<<agg_blocks, 256>>>(b1, nullptr);
    edge_scatter_kernel<true><<<edge_blocks, 256>>>(ei, nullptr);

    gemm_bf16x3<true, true, 2><<<gemm_grid, 256>>>(nullptr, NN);
    init_agg_kernel<false><<<agg_blocks, 256>>>(b2, out);
    edge_scatter_kernel<false><<<edge_blocks, 256>>>(ei, out);
}

// round 9
// speedup vs baseline: 1.9229x; 1.0353x over previous
#include <cuda_runtime.h>
#include <cuda_bf16.h>
#include <cstdint>

#define NN 50000
#define DD 512
#define EE 150000

#define BM 128
#define BN 128
#define BK 32
#define SA 40          // smem row stride in bf16 elems (80B -> conflict-free ldmatrix)

// ---------------------------------------------------------------------------
// Device globals (no allocation anywhere)
// ---------------------------------------------------------------------------
__device__ __align__(16) float g_bufA[(size_t)NN * DD];   // scaled messages hs
__device__ __align__(16) float g_bufB[(size_t)NN * DD];   // layer-1 aggregate
__device__ __align__(16) __nv_bfloat16 g_W1h[DD * DD], g_W1l[DD * DD];
__device__ __align__(16) __nv_bfloat16 g_W2h[DD * DD], g_W2l[DD * DD];
__device__ float g_deg[NN];
__device__ float g_dis[NN];
__device__ int   g_is64;

// ---------------------------------------------------------------------------
// PTX helpers (legal on plain sm_103 target: ldmatrix/mma.sync are sm_80+)
// ---------------------------------------------------------------------------
__device__ __forceinline__ uint32_t smem_u32(const void* p) {
    uint32_t a;
    asm("{ .reg .u64 t; cvta.to.shared.u64 t, %1; cvt.u32.u64 %0, t; }"
        : "=r"(a) : "l"(p));
    return a;
}
#define LDM4(d, addr)                                                           \
    asm volatile("ldmatrix.sync.aligned.m8n8.x4.shared.b16 {%0,%1,%2,%3}, [%4];"\
        : "=r"((d)[0]), "=r"((d)[1]), "=r"((d)[2]), "=r"((d)[3]) : "r"(addr))
#define MMA(cc, aa, b0, b1)                                                     \
    asm volatile("mma.sync.aligned.m16n8k16.row.col.f32.bf16.bf16.f32 "         \
        "{%0,%1,%2,%3}, {%4,%5,%6,%7}, {%8,%9}, {%0,%1,%2,%3};"                 \
        : "+f"((cc)[0]), "+f"((cc)[1]), "+f"((cc)[2]), "+f"((cc)[3])            \
        : "r"((aa)[0]), "r"((aa)[1]), "r"((aa)[2]), "r"((aa)[3]),               \
          "r"(b0), "r"(b1))

__device__ __forceinline__ uint32_t pack_bf16(__nv_bfloat16 a, __nv_bfloat16 b) {
    __nv_bfloat162 t; t.x = a; t.y = b;
    return *reinterpret_cast<uint32_t*>(&t);
}
__device__ __forceinline__ int load_idx(const void* __restrict__ ei, int pos) {
    if (g_is64) return (int)((const long long*)ei)[pos];
    return ((const int*)ei)[pos];
}

// ---------------------------------------------------------------------------
// k1: dtype detect (block 0) + deg init (all blocks)
// ---------------------------------------------------------------------------
__global__ void k1_detect_initdeg(const unsigned int* __restrict__ w) {
    if (blockIdx.x == 0 && threadIdx.x == 0) {
        int is64 = 1;
        for (int i = 0; i < 128; i++)
            if (w[2 * i + 1] != 0u) { is64 = 0; break; }
        g_is64 = is64;
    }
    int i = blockIdx.x * blockDim.x + threadIdx.x;
    if (i < NN) g_deg[i] = 1.0f;   // self-loop contributes 1
}

// k2: degree count
__global__ void k2_count_deg(const void* __restrict__ ei) {
    int e = blockIdx.x * blockDim.x + threadIdx.x;
    if (e < EE) atomicAdd(&g_deg[load_idx(ei, EE + e)], 1.0f);
}

// ---------------------------------------------------------------------------
// k3: calc_dis (blocks [0,196)) + W1 split (blocks [196,452)) + W2 split
//     ([452,708)).  W split: Wh[n][k] = bf16(W[k][n]), Wl = bf16(residual).
// ---------------------------------------------------------------------------
__global__ void k3_dis_wsplit(const float* __restrict__ W1,
                              const float* __restrict__ W2)
{
    int b = blockIdx.x;
    int tid = threadIdx.x;
    if (b < 196) {
        int i = b * 256 + tid;
        if (i < NN) g_dis[i] = rsqrtf(g_deg[i]);
        return;
    }
    int layer = (b < 452) ? 1 : 2;
    int t = (layer == 1) ? (b - 196) : (b - 452);     // 0..255 -> 16x16 tiles
    const float* __restrict__ W = (layer == 1) ? W1 : W2;
    __nv_bfloat16* __restrict__ Wh = (layer == 1) ? g_W1h : g_W2h;   // device code:
    __nv_bfloat16* __restrict__ Wl = (layer == 1) ? g_W1l : g_W2l;   // real dev addrs

    __shared__ float tt[32][33];
    int k0 = (t & 15) * 32, n0 = (t >> 4) * 32;
    int tx = tid & 31, ty = tid >> 5;                 // 32 x 8
    for (int s = 0; s < 4; s++) {
        int j = ty + 8 * s;
        tt[j][tx] = W[(size_t)(k0 + j) * DD + n0 + tx];
    }
    __syncthreads();
    for (int s = 0; s < 4; s++) {
        int j = ty + 8 * s;
        float a = tt[tx][j];                          // = W[k0+tx][n0+j]
        __nv_bfloat16 h = __float2bfloat16(a);
        float lo = a - __bfloat162float(h);
        Wh[(size_t)(n0 + j) * DD + k0 + tx] = h;
        Wl[(size_t)(n0 + j) * DD + k0 + tx] = __float2bfloat16(lo);
    }
}

// ---------------------------------------------------------------------------
// bf16x3 tensor-core GEMM with fused aggregation epilogue.
//   h = op(A) @ W      (op = optional relu; W selected by LAYER in device code)
//   g_bufA[row][:] = h * dis[row]          (pre-scaled messages)
//   dest[row][:] = h * dis[row]^2 + bias   (self-loop + bias; scatter adds rest)
// 8 warps: warp grid 4(m) x 2(n); warp tile 32x64; mma m16n8k16
// ---------------------------------------------------------------------------
template <bool A_BUFB, bool RELU, int LAYER>
__global__ __launch_bounds__(256, 1) void gemm_bf16x3(
    const float* __restrict__ Aext,
    const float* __restrict__ bias, float* __restrict__ dest_ext, int M)
{
    const float* __restrict__ A = A_BUFB ? (const float*)g_bufB : Aext;
    const __nv_bfloat16* __restrict__ Wh = (LAYER == 1) ? g_W1h : g_W2h;
    const __nv_bfloat16* __restrict__ Wl = (LAYER == 1) ? g_W1l : g_W2l;
    float* __restrict__ dest = A_BUFB ? dest_ext : (float*)g_bufB;
    float* __restrict__ HS = g_bufA;

    __shared__ __align__(16) uint16_t Ash[BM * SA], Asl[BM * SA];
    __shared__ __align__(16) uint16_t Bsh[BN * SA], Bsl[BN * SA];

    const int tid = threadIdx.x, lane = tid & 31, wid = tid >> 5;
    const int wm = (wid & 3) * 32;
    const int wn = (wid >> 2) * 64;
    const int bm = blockIdx.y * BM;
    const int n0 = blockIdx.x * BN;

    float4 pa[4];
    uint4  pbh[2], pbl[2];

    auto prefetch = [&](int k0) {
#pragma unroll
        for (int r = 0; r < 4; r++) {
            int idx = tid + 256 * r;
            int row = idx >> 3, c4 = idx & 7;
            int g = bm + row;
            float4 v = make_float4(0.f, 0.f, 0.f, 0.f);
            if (g < M) v = *(const float4*)&A[(size_t)g * DD + k0 + c4 * 4];
            pa[r] = v;
        }
#pragma unroll
        for (int r = 0; r < 2; r++) {
            int idx = tid + 256 * r;
            int row = idx >> 2, c = idx & 3;
            size_t g = (size_t)(n0 + row) * DD + k0 + c * 8;
            pbh[r] = *(const uint4*)&Wh[g];
            pbl[r] = *(const uint4*)&Wl[g];
        }
    };
    auto commit = [&]() {
#pragma unroll
        for (int r = 0; r < 4; r++) {
            int idx = tid + 256 * r;
            int row = idx >> 3, c4 = idx & 7;
            float4 v = pa[r];
            if (RELU) {
                v.x = fmaxf(v.x, 0.f); v.y = fmaxf(v.y, 0.f);
                v.z = fmaxf(v.z, 0.f); v.w = fmaxf(v.w, 0.f);
            }
            __nv_bfloat16 hx = __float2bfloat16(v.x);
            __nv_bfloat16 hy = __float2bfloat16(v.y);
            __nv_bfloat16 hz = __float2bfloat16(v.z);
            __nv_bfloat16 hw = __float2bfloat16(v.w);
            __nv_bfloat16 lx = __float2bfloat16(v.x - __bfloat162float(hx));
            __nv_bfloat16 ly = __float2bfloat16(v.y - __bfloat162float(hy));
            __nv_bfloat16 lz = __float2bfloat16(v.z - __bfloat162float(hz));
            __nv_bfloat16 lw = __float2bfloat16(v.w - __bfloat162float(hw));
            *(uint2*)&Ash[row * SA + c4 * 4] =
                make_uint2(pack_bf16(hx, hy), pack_bf16(hz, hw));
            *(uint2*)&Asl[row * SA + c4 * 4] =
                make_uint2(pack_bf16(lx, ly), pack_bf16(lz, lw));
        }
#pragma unroll
        for (int r = 0; r < 2; r++) {
            int idx = tid + 256 * r;
            int row = idx >> 2, c = idx & 3;
            *(uint4*)&Bsh[row * SA + c * 8] = pbh[r];
            *(uint4*)&Bsl[row * SA + c * 8] = pbl[r];
        }
    };

    const uint32_t aB = smem_u32(Ash), aL = smem_u32(Asl);
    const uint32_t bB = smem_u32(Bsh), bL = smem_u32(Bsl);

    float c[2][8][4];
#pragma unroll
    for (int i = 0; i < 2; i++)
#pragma unroll
        for (int j = 0; j < 8; j++)
#pragma unroll
            for (int q = 0; q < 4; q++) c[i][j][q] = 0.0f;

    prefetch(0);
    commit();
    __syncthreads();

    for (int it = 0; it < DD / BK; it++) {
        if (it < DD / BK - 1) prefetch((it + 1) * BK);

#pragma unroll
        for (int ks = 0; ks < 2; ks++) {
            const int k0s = ks * 16;
            uint32_t ah[2][4], al[2][4];
#pragma unroll
            for (int mi = 0; mi < 2; mi++) {
                uint32_t off = (uint32_t)(((wm + mi * 16 + (lane & 15)) * SA
                                + k0s + 8 * (lane >> 4)) * 2);
                LDM4(ah[mi], aB + off);
                LDM4(al[mi], aL + off);
            }
            uint32_t bh[4][4], bl[4][4];
#pragma unroll
            for (int nj = 0; nj < 4; nj++) {
                uint32_t off = (uint32_t)(((wn + nj * 16 + (lane & 7)
                                + 8 * (lane >> 4)) * SA
                                + k0s + 8 * ((lane >> 3) & 1)) * 2);
                LDM4(bh[nj], bB + off);
                LDM4(bl[nj], bL + off);
            }
#pragma unroll
            for (int mi = 0; mi < 2; mi++)
#pragma unroll
                for (int nj = 0; nj < 4; nj++) {
                    MMA(c[mi][nj * 2],     ah[mi], bh[nj][0], bh[nj][1]);
                    MMA(c[mi][nj * 2],     ah[mi], bl[nj][0], bl[nj][1]);
                    MMA(c[mi][nj * 2],     al[mi], bh[nj][0], bh[nj][1]);
                    MMA(c[mi][nj * 2 + 1], ah[mi], bh[nj][2], bh[nj][3]);
                    MMA(c[mi][nj * 2 + 1], ah[mi], bl[nj][2], bl[nj][3]);
                    MMA(c[mi][nj * 2 + 1], al[mi], bh[nj][2], bh[nj][3]);
                }
        }
        __syncthreads();
        if (it < DD / BK - 1) {
            commit();
            __syncthreads();
        }
    }

    // Fused epilogue: hs = h*dis, agg = h*dis^2 + bias
#pragma unroll
    for (int mi = 0; mi < 2; mi++) {
        int r0 = bm + wm + mi * 16 + (lane >> 2);
        int r1 = r0 + 8;
        float d0 = (r0 < M) ? g_dis[r0] : 0.f;
        float d1 = (r1 < M) ? g_dis[r1] : 0.f;
#pragma unroll
        for (int nj = 0; nj < 8; nj++) {
            int col = n0 + wn + nj * 8 + (lane & 3) * 2;
            float2 bv = *(const float2*)&bias[col];
            if (r0 < M) {
                float h0 = c[mi][nj][0] * d0, h1 = c[mi][nj][1] * d0;
                *(float2*)&HS[(size_t)r0 * DD + col] = make_float2(h0, h1);
                *(float2*)&dest[(size_t)r0 * DD + col] =
                    make_float2(fmaf(h0, d0, bv.x), fmaf(h1, d0, bv.y));
            }
            if (r1 < M) {
                float h0 = c[mi][nj][2] * d1, h1 = c[mi][nj][3] * d1;
                *(float2*)&HS[(size_t)r1 * DD + col] = make_float2(h0, h1);
                *(float2*)&dest[(size_t)r1 * DD + col] =
                    make_float2(fmaf(h0, d1, bv.x), fmaf(h1, d1, bv.y));
            }
        }
    }
}

// ---------------------------------------------------------------------------
// Edge scatter: agg[dst,:] += dis[dst] * hs[src,:]   (hs pre-scaled by dis[src])
// ---------------------------------------------------------------------------
template <bool TO_BUFB>
__global__ __launch_bounds__(256) void edge_scatter_kernel(
    const void* __restrict__ ei, float* __restrict__ agg_ext)
{
    float* __restrict__ agg = TO_BUFB ? (float*)g_bufB : agg_ext;
    const float* __restrict__ hs = g_bufA;
    int warp = (blockIdx.x * blockDim.x + threadIdx.x) >> 5;
    int lane = threadIdx.x & 31;
    if (warp >= EE) return;
    int s = load_idx(ei, warp);
    int d = load_idx(ei, EE + warp);
    float w = g_dis[d];
    const float4* hr = (const float4*)(hs + (size_t)s * DD);
    float* ar = agg + (size_t)d * DD;
#pragma unroll
    for (int i = 0; i < 4; i++) {
        int c4 = lane + i * 32;
        float4 v = hr[c4];
        float* p = ar + c4 * 4;
        asm volatile("red.global.add.v4.f32 [%0], {%1,%2,%3,%4};"
                     :: "l"(p), "f"(v.x * w), "f"(v.y * w),
                        "f"(v.z * w), "f"(v.w * w) : "memory");
    }
}

// ---------------------------------------------------------------------------
// Launch (kernel launches only — graph-capturable).
// Order chosen so launch #4 (= ncu's profiled slot) is gemm1.
// ---------------------------------------------------------------------------
extern "C" void kernel_launch(void* const* d_in, const int* in_sizes, int n_in,
                              void* d_out, int out_size)
{
    const float* x  = (const float*)d_in[0];
    const void*  ei = d_in[1];
    const float* W1 = (const float*)d_in[2];
    const float* b1 = (const float*)d_in[3];
    const float* W2 = (const float*)d_in[4];
    const float* b2 = (const float*)d_in[5];
    float* out = (float*)d_out;

    dim3 gemm_grid(DD / BN, (NN + BM - 1) / BM);   // (4, 391)
    const int edge_blocks = (EE + 7) / 8;

    k1_detect_initdeg<<<196, 256>>>((const unsigned int*)ei);          // #1
    k2_count_deg<<<(EE + 255) / 256, 256>>>(ei);                       // #2
    k3_dis_wsplit<<<708, 256>>>(W1, W2);                               // #3

    // Layer 1: h1 = x@W1 ; bufA=hs1, bufB=self-loop+bias ; scatter adds edges
    gemm_bf16x3<false, false, 1><<<gemm_grid, 256>>>(x, b1, nullptr, NN);  // #4
    edge_scatter_kernel<true><<<edge_blocks, 256>>>(ei, nullptr);          // #5

    // Layer 2: h2 = relu(bufB)@W2 ; bufA=hs2, out=self-loop+bias ; scatter
    gemm_bf16x3<true, true, 2><<<gemm_grid, 256>>>(nullptr, b2, out, NN);  // #6
    edge_scatter_kernel<false><<<edge_blocks, 256>>>(ei, out);             // #7
}

// round 10
// speedup vs baseline: 1.9545x; 1.0165x over previous
#include <cuda_runtime.h>
#include <cuda_bf16.h>
#include <cstdint>

#define NN 50000
#define DD 512
#define EE 150000

#define BM 128
#define BN 256
#define BK 32
#define SA 40              // smem row stride in bf16 (80B rows -> conflict-free ldmatrix)
#define NIT (DD / BK)      // 16

// Stage layout (bytes): Ah 10240 | Al 10240 | Bh 20480 | Bl 20480
#define ST_AL 10240
#define ST_BH 20480
#define ST_BL 40960
#define STAGE 61440
#define SMEM_DYN (2 * STAGE)   // 122880

// ---------------------------------------------------------------------------
// Device globals (no allocation anywhere)
// ---------------------------------------------------------------------------
__device__ __align__(16) float g_bufA[(size_t)NN * DD];   // scaled messages hs
__device__ __align__(16) float g_bufB[(size_t)NN * DD];   // layer-1 aggregate
__device__ __align__(16) __nv_bfloat16 g_W1h[DD * DD], g_W1l[DD * DD];
__device__ __align__(16) __nv_bfloat16 g_W2h[DD * DD], g_W2l[DD * DD];
__device__ float g_deg[NN];
__device__ float g_dis[NN];
__device__ int   g_is64;

// ---------------------------------------------------------------------------
// PTX helpers (ldmatrix / mma.sync / cp.async are sm_80+, legal on plain sm_103)
// ---------------------------------------------------------------------------
__device__ __forceinline__ uint32_t smem_u32(const void* p) {
    uint32_t a;
    asm("{ .reg .u64 t; cvta.to.shared.u64 t, %1; cvt.u32.u64 %0, t; }"
        : "=r"(a) : "l"(p));
    return a;
}
#define LDM4(d, addr)                                                           \
    asm volatile("ldmatrix.sync.aligned.m8n8.x4.shared.b16 {%0,%1,%2,%3}, [%4];"\
        : "=r"((d)[0]), "=r"((d)[1]), "=r"((d)[2]), "=r"((d)[3]) : "r"(addr))
#define MMA(cc, aa, b0, b1)                                                     \
    asm volatile("mma.sync.aligned.m16n8k16.row.col.f32.bf16.bf16.f32 "         \
        "{%0,%1,%2,%3}, {%4,%5,%6,%7}, {%8,%9}, {%0,%1,%2,%3};"                 \
        : "+f"((cc)[0]), "+f"((cc)[1]), "+f"((cc)[2]), "+f"((cc)[3])            \
        : "r"((aa)[0]), "r"((aa)[1]), "r"((aa)[2]), "r"((aa)[3]),               \
          "r"(b0), "r"(b1))
#define CPASYNC16(sm, gm)                                                       \
    asm volatile("cp.async.cg.shared.global [%0], [%1], 16;"                    \
                 :: "r"(sm), "l"(gm) : "memory")
#define CPCOMMIT()  asm volatile("cp.async.commit_group;" ::: "memory")
#define CPWAIT0()   asm volatile("cp.async.wait_group 0;" ::: "memory")

__device__ __forceinline__ uint32_t pack_bf16(__nv_bfloat16 a, __nv_bfloat16 b) {
    __nv_bfloat162 t; t.x = a; t.y = b;
    return *reinterpret_cast<uint32_t*>(&t);
}
__device__ __forceinline__ int load_idx(const void* __restrict__ ei, int pos) {
    if (g_is64) return (int)((const long long*)ei)[pos];
    return ((const int*)ei)[pos];
}

// ---------------------------------------------------------------------------
// k1: dtype detect (block 0) + deg init
// ---------------------------------------------------------------------------
__global__ void k1_detect_initdeg(const unsigned int* __restrict__ w) {
    if (blockIdx.x == 0 && threadIdx.x == 0) {
        int is64 = 1;
        for (int i = 0; i < 128; i++)
            if (w[2 * i + 1] != 0u) { is64 = 0; break; }
        g_is64 = is64;
    }
    int i = blockIdx.x * blockDim.x + threadIdx.x;
    if (i < NN) g_deg[i] = 1.0f;
}

__global__ void k2_count_deg(const void* __restrict__ ei) {
    int e = blockIdx.x * blockDim.x + threadIdx.x;
    if (e < EE) atomicAdd(&g_deg[load_idx(ei, EE + e)], 1.0f);
}

// ---------------------------------------------------------------------------
// k3: calc_dis ([0,196)) + W1 split ([196,452)) + W2 split ([452,708))
//     Wh[n][k] = bf16(W[k][n]), Wl = bf16(residual)
// ---------------------------------------------------------------------------
__global__ void k3_dis_wsplit(const float* __restrict__ W1,
                              const float* __restrict__ W2)
{
    int b = blockIdx.x;
    int tid = threadIdx.x;
    if (b < 196) {
        int i = b * 256 + tid;
        if (i < NN) g_dis[i] = rsqrtf(g_deg[i]);
        return;
    }
    int layer = (b < 452) ? 1 : 2;
    int t = (layer == 1) ? (b - 196) : (b - 452);
    const float* __restrict__ W = (layer == 1) ? W1 : W2;
    __nv_bfloat16* __restrict__ Wh = (layer == 1) ? g_W1h : g_W2h;
    __nv_bfloat16* __restrict__ Wl = (layer == 1) ? g_W1l : g_W2l;

    __shared__ float tt[32][33];
    int k0 = (t & 15) * 32, n0 = (t >> 4) * 32;
    int tx = tid & 31, ty = tid >> 5;
    for (int s = 0; s < 4; s++) {
        int j = ty + 8 * s;
        tt[j][tx] = W[(size_t)(k0 + j) * DD + n0 + tx];
    }
    __syncthreads();
    for (int s = 0; s < 4; s++) {
        int j = ty + 8 * s;
        float a = tt[tx][j];
        __nv_bfloat16 h = __float2bfloat16(a);
        float lo = a - __bfloat162float(h);
        Wh[(size_t)(n0 + j) * DD + k0 + tx] = h;
        Wl[(size_t)(n0 + j) * DD + k0 + tx] = __float2bfloat16(lo);
    }
}

// ---------------------------------------------------------------------------
// bf16x3 tensor-core GEMM, CTA tile 128x256, warp tile 64x64 (2m x 4n warps),
// double-buffered smem, B via cp.async, fused aggregation epilogue:
//   h = op(A) @ W ; HS = h*dis ; dest = h*dis^2 + bias
// ---------------------------------------------------------------------------
template <bool A_BUFB, bool RELU, int LAYER>
__global__ __launch_bounds__(256, 1) void gemm_bf16x3(
    const float* __restrict__ Aext,
    const float* __restrict__ bias, float* __restrict__ dest_ext, int M)
{
    extern __shared__ __align__(16) char smem[];
    const float* __restrict__ A = A_BUFB ? (const float*)g_bufB : Aext;
    const __nv_bfloat16* __restrict__ Wh = (LAYER == 1) ? g_W1h : g_W2h;
    const __nv_bfloat16* __restrict__ Wl = (LAYER == 1) ? g_W1l : g_W2l;
    float* __restrict__ dest = A_BUFB ? dest_ext : (float*)g_bufB;
    float* __restrict__ HS = g_bufA;

    const uint32_t sb = smem_u32(smem);
    const int tid = threadIdx.x, lane = tid & 31, wid = tid >> 5;
    const int wm = (wid & 1) * 64;       // 2 warps in m
    const int wn = (wid >> 1) * 64;      // 4 warps in n
    const int bm = blockIdx.y * BM;
    const int n0 = blockIdx.x * BN;

    // A loader indices: 1024 float4 per tile, 4/thread
    const int a_row = tid >> 3, a_c4 = tid & 7;          // +32 rows per r
    // B loader: 1024 16B-chunks per (hi|lo) buffer, 4/thread
    const int b_row = tid >> 2, b_c = tid & 3;           // +64 rows per r

    float4 pa[4];

    auto issue_B = [&](int k0, int st) {
        uint32_t bh = sb + st * STAGE + ST_BH;
        uint32_t bl = sb + st * STAGE + ST_BL;
#pragma unroll
        for (int r = 0; r < 4; r++) {
            int row = b_row + 64 * r;
            size_t g = (size_t)(n0 + row) * DD + k0 + b_c * 8;
            uint32_t so = (uint32_t)(row * SA + b_c * 8) * 2;
            CPASYNC16(bh + so, (const void*)&Wh[g]);
            CPASYNC16(bl + so, (const void*)&Wl[g]);
        }
        CPCOMMIT();
    };
    auto issue_A = [&](int k0) {
#pragma unroll
        for (int r = 0; r < 4; r++) {
            int row = a_row + 32 * r;
            int g = bm + row;
            float4 v = make_float4(0.f, 0.f, 0.f, 0.f);
            if (g < M) v = *(const float4*)&A[(size_t)g * DD + k0 + a_c4 * 4];
            pa[r] = v;
        }
    };
    auto commit_A = [&](int st) {
        uint32_t ah = sb + st * STAGE;
        uint32_t al = ah + ST_AL;
#pragma unroll
        for (int r = 0; r < 4; r++) {
            int row = a_row + 32 * r;
            float4 v = pa[r];
            if (RELU) {
                v.x = fmaxf(v.x, 0.f); v.y = fmaxf(v.y, 0.f);
                v.z = fmaxf(v.z, 0.f); v.w = fmaxf(v.w, 0.f);
            }
            __nv_bfloat16 hx = __float2bfloat16(v.x);
            __nv_bfloat16 hy = __float2bfloat16(v.y);
            __nv_bfloat16 hz = __float2bfloat16(v.z);
            __nv_bfloat16 hw = __float2bfloat16(v.w);
            __nv_bfloat16 lx = __float2bfloat16(v.x - __bfloat162float(hx));
            __nv_bfloat16 ly = __float2bfloat16(v.y - __bfloat162float(hy));
            __nv_bfloat16 lz = __float2bfloat16(v.z - __bfloat162float(hz));
            __nv_bfloat16 lw = __float2bfloat16(v.w - __bfloat162float(hw));
            uint32_t so = (uint32_t)(row * SA + a_c4 * 4) * 2;
            asm volatile("st.shared.v2.b32 [%0], {%1,%2};" ::
                "r"(ah + so), "r"(pack_bf16(hx, hy)), "r"(pack_bf16(hz, hw))
                : "memory");
            asm volatile("st.shared.v2.b32 [%0], {%1,%2};" ::
                "r"(al + so), "r"(pack_bf16(lx, ly)), "r"(pack_bf16(lz, lw))
                : "memory");
        }
    };

    float c[4][8][4];
#pragma unroll
    for (int i = 0; i < 4; i++)
#pragma unroll
        for (int j = 0; j < 8; j++)
#pragma unroll
            for (int q = 0; q < 4; q++) c[i][j][q] = 0.0f;

    // Prologue: fill stage 0
    issue_B(0, 0);
    issue_A(0);
    commit_A(0);
    CPWAIT0();
    __syncthreads();

    for (int it = 0; it < NIT; it++) {
        const int st = it & 1;
        const bool more = (it + 1 < NIT);
        if (more) {
            issue_B((it + 1) * BK, st ^ 1);
            issue_A((it + 1) * BK);
        }

        const uint32_t ahB = sb + st * STAGE;
        const uint32_t alB = ahB + ST_AL;
        const uint32_t bhB = sb + st * STAGE + ST_BH;
        const uint32_t blB = sb + st * STAGE + ST_BL;

#pragma unroll
        for (int ks = 0; ks < 2; ks++) {
            const int k0s = ks * 16;
            uint32_t ah[4][4], al[4][4];
#pragma unroll
            for (int mi = 0; mi < 4; mi++) {
                uint32_t off = (uint32_t)(((wm + mi * 16 + (lane & 15)) * SA
                                + k0s + 8 * (lane >> 4)) * 2);
                LDM4(ah[mi], ahB + off);
                LDM4(al[mi], alB + off);
            }
#pragma unroll
            for (int nj = 0; nj < 4; nj++) {
                uint32_t bh[4], bl[4];
                uint32_t off = (uint32_t)(((wn + nj * 16 + (lane & 7)
                                + 8 * (lane >> 4)) * SA
                                + k0s + 8 * ((lane >> 3) & 1)) * 2);
                LDM4(bh, bhB + off);
                LDM4(bl, blB + off);
#pragma unroll
                for (int mi = 0; mi < 4; mi++) {
                    MMA(c[mi][nj * 2],     ah[mi], bh[0], bh[1]);
                    MMA(c[mi][nj * 2],     ah[mi], bl[0], bl[1]);
                    MMA(c[mi][nj * 2],     al[mi], bh[0], bh[1]);
                    MMA(c[mi][nj * 2 + 1], ah[mi], bh[2], bh[3]);
                    MMA(c[mi][nj * 2 + 1], ah[mi], bl[2], bl[3]);
                    MMA(c[mi][nj * 2 + 1], al[mi], bh[2], bh[3]);
                }
            }
        }
        if (more) {
            commit_A(st ^ 1);
            CPWAIT0();
        }
        __syncthreads();
    }

    // Fused epilogue: hs = h*dis, dest = h*dis^2 + bias
#pragma unroll
    for (int mi = 0; mi < 4; mi++) {
        int r0 = bm + wm + mi * 16 + (lane >> 2);
        int r1 = r0 + 8;
        float d0 = (r0 < M) ? g_dis[r0] : 0.f;
        float d1 = (r1 < M) ? g_dis[r1] : 0.f;
#pragma unroll
        for (int nj2 = 0; nj2 < 8; nj2++) {
            int col = n0 + wn + nj2 * 8 + (lane & 3) * 2;
            float2 bv = *(const float2*)&bias[col];
            if (r0 < M) {
                float h0 = c[mi][nj2][0] * d0, h1 = c[mi][nj2][1] * d0;
                *(float2*)&HS[(size_t)r0 * DD + col] = make_float2(h0, h1);
                *(float2*)&dest[(size_t)r0 * DD + col] =
                    make_float2(fmaf(h0, d0, bv.x), fmaf(h1, d0, bv.y));
            }
            if (r1 < M) {
                float h0 = c[mi][nj2][2] * d1, h1 = c[mi][nj2][3] * d1;
                *(float2*)&HS[(size_t)r1 * DD + col] = make_float2(h0, h1);
                *(float2*)&dest[(size_t)r1 * DD + col] =
                    make_float2(fmaf(h0, d1, bv.x), fmaf(h1, d1, bv.y));
            }
        }
    }
}

// ---------------------------------------------------------------------------
// Edge scatter: agg[dst,:] += dis[dst] * hs[src,:]
// ---------------------------------------------------------------------------
template <bool TO_BUFB>
__global__ __launch_bounds__(256) void edge_scatter_kernel(
    const void* __restrict__ ei, float* __restrict__ agg_ext)
{
    float* __restrict__ agg = TO_BUFB ? (float*)g_bufB : agg_ext;
    const float* __restrict__ hs = g_bufA;
    int warp = (blockIdx.x * blockDim.x + threadIdx.x) >> 5;
    int lane = threadIdx.x & 31;
    if (warp >= EE) return;
    int s = load_idx(ei, warp);
    int d = load_idx(ei, EE + warp);
    float w = g_dis[d];
    const float4* hr = (const float4*)(hs + (size_t)s * DD);
    float* ar = agg + (size_t)d * DD;
#pragma unroll
    for (int i = 0; i < 4; i++) {
        int c4 = lane + i * 32;
        float4 v = hr[c4];
        float* p = ar + c4 * 4;
        asm volatile("red.global.add.v4.f32 [%0], {%1,%2,%3,%4};"
                     :: "l"(p), "f"(v.x * w), "f"(v.y * w),
                        "f"(v.z * w), "f"(v.w * w) : "memory");
    }
}

// ---------------------------------------------------------------------------
// >48KB dynamic smem opt-in (non-stream API: capture-safe; also at static init)
// ---------------------------------------------------------------------------
static void set_smem_attrs() {
    cudaFuncSetAttribute(gemm_bf16x3<false, false, 1>,
                         cudaFuncAttributeMaxDynamicSharedMemorySize, SMEM_DYN);
    cudaFuncSetAttribute(gemm_bf16x3<true, true, 2>,
                         cudaFuncAttributeMaxDynamicSharedMemorySize, SMEM_DYN);
}
namespace { struct GInit { GInit() { set_smem_attrs(); } } g_init; }

// ---------------------------------------------------------------------------
// Launch (graph-capturable; launch #4 = gemm1 for ncu's profiled slot)
// ---------------------------------------------------------------------------
extern "C" void kernel_launch(void* const* d_in, const int* in_sizes, int n_in,
                              void* d_out, int out_size)
{
    const float* x  = (const float*)d_in[0];
    const void*  ei = d_in[1];
    const float* W1 = (const float*)d_in[2];
    const float* b1 = (const float*)d_in[3];
    const float* W2 = (const float*)d_in[4];
    const float* b2 = (const float*)d_in[5];
    float* out = (float*)d_out;

    set_smem_attrs();

    dim3 gemm_grid(DD / BN, (NN + BM - 1) / BM);   // (2, 391)
    const int edge_blocks = (EE + 7) / 8;

    k1_detect_initdeg<<<196, 256>>>((const unsigned int*)ei);              // #1
    k2_count_deg<<<(EE + 255) / 256, 256>>>(ei);                           // #2
    k3_dis_wsplit<<<708, 256>>>(W1, W2);                                   // #3

    gemm_bf16x3<false, false, 1><<<gemm_grid, 256, SMEM_DYN>>>(x, b1, nullptr, NN); // #4
    edge_scatter_kernel<true><<<edge_blocks, 256>>>(ei, nullptr);                   // #5

    gemm_bf16x3<true, true, 2><<<gemm_grid, 256, SMEM_DYN>>>(nullptr, b2, out, NN); // #6
    edge_scatter_kernel<false><<<edge_blocks, 256>>>(ei, out);                      // #7
}

// round 11
// speedup vs baseline: 2.0110x; 1.0289x over previous
#include <cuda_runtime.h>
#include <cuda_bf16.h>
#include <cstdint>

#define NN 50000
#define DD 512
#define EE 150000

#define BM 64
#define BN 128
#define BK 32
#define SA 40              // smem row stride in bf16 (80B rows -> conflict-free ldmatrix)
#define NIT (DD / BK)      // 16

// Stage layout (bytes): Ah 5120 | Al 5120 | Bh 10240 | Bl 10240
#define ST_AL 5120
#define ST_BH 10240
#define ST_BL 20480
#define STAGE 30720
#define SMEM_DYN (2 * STAGE)   // 61440 per CTA; 2 CTAs/SM = 122880

// ---------------------------------------------------------------------------
// Device globals (no allocation anywhere)
// ---------------------------------------------------------------------------
__device__ __align__(16) float g_bufA[(size_t)NN * DD];   // scaled messages hs
__device__ __align__(16) float g_bufB[(size_t)NN * DD];   // layer-1 aggregate
__device__ __align__(16) __nv_bfloat16 g_W1h[DD * DD], g_W1l[DD * DD];
__device__ __align__(16) __nv_bfloat16 g_W2h[DD * DD], g_W2l[DD * DD];
__device__ float g_deg[NN];
__device__ float g_dis[NN];
__device__ int   g_is64;

// ---------------------------------------------------------------------------
// PTX helpers (ldmatrix / mma.sync / cp.async are sm_80+, legal on plain sm_103)
// ---------------------------------------------------------------------------
__device__ __forceinline__ uint32_t smem_u32(const void* p) {
    uint32_t a;
    asm("{ .reg .u64 t; cvta.to.shared.u64 t, %1; cvt.u32.u64 %0, t; }"
        : "=r"(a) : "l"(p));
    return a;
}
#define LDM4(d, addr)                                                           \
    asm volatile("ldmatrix.sync.aligned.m8n8.x4.shared.b16 {%0,%1,%2,%3}, [%4];"\
        : "=r"((d)[0]), "=r"((d)[1]), "=r"((d)[2]), "=r"((d)[3]) : "r"(addr))
#define MMA(cc, aa, b0, b1)                                                     \
    asm volatile("mma.sync.aligned.m16n8k16.row.col.f32.bf16.bf16.f32 "         \
        "{%0,%1,%2,%3}, {%4,%5,%6,%7}, {%8,%9}, {%0,%1,%2,%3};"                 \
        : "+f"((cc)[0]), "+f"((cc)[1]), "+f"((cc)[2]), "+f"((cc)[3])            \
        : "r"((aa)[0]), "r"((aa)[1]), "r"((aa)[2]), "r"((aa)[3]),               \
          "r"(b0), "r"(b1))
#define CPASYNC16(sm, gm)                                                       \
    asm volatile("cp.async.cg.shared.global [%0], [%1], 16;"                    \
                 :: "r"(sm), "l"(gm) : "memory")
#define CPCOMMIT()  asm volatile("cp.async.commit_group;" ::: "memory")
#define CPWAIT0()   asm volatile("cp.async.wait_group 0;" ::: "memory")

__device__ __forceinline__ uint32_t pack_bf16(__nv_bfloat16 a, __nv_bfloat16 b) {
    __nv_bfloat162 t; t.x = a; t.y = b;
    return *reinterpret_cast<uint32_t*>(&t);
}
__device__ __forceinline__ int load_idx(const void* __restrict__ ei, int pos) {
    if (g_is64) return (int)((const long long*)ei)[pos];
    return ((const int*)ei)[pos];
}

// ---------------------------------------------------------------------------
// k1: dtype detect (block 0) + deg init
// ---------------------------------------------------------------------------
__global__ void k1_detect_initdeg(const unsigned int* __restrict__ w) {
    if (blockIdx.x == 0 && threadIdx.x == 0) {
        int is64 = 1;
        for (int i = 0; i < 128; i++)
            if (w[2 * i + 1] != 0u) { is64 = 0; break; }
        g_is64 = is64;
    }
    int i = blockIdx.x * blockDim.x + threadIdx.x;
    if (i < NN) g_deg[i] = 1.0f;
}

__global__ void k2_count_deg(const void* __restrict__ ei) {
    int e = blockIdx.x * blockDim.x + threadIdx.x;
    if (e < EE) atomicAdd(&g_deg[load_idx(ei, EE + e)], 1.0f);
}

// ---------------------------------------------------------------------------
// k3: calc_dis ([0,196)) + W1 split ([196,452)) + W2 split ([452,708))
//     Wh[n][k] = bf16(W[k][n]), Wl = bf16(residual)
// ---------------------------------------------------------------------------
__global__ void k3_dis_wsplit(const float* __restrict__ W1,
                              const float* __restrict__ W2)
{
    int b = blockIdx.x;
    int tid = threadIdx.x;
    if (b < 196) {
        int i = b * 256 + tid;
        if (i < NN) g_dis[i] = rsqrtf(g_deg[i]);
        return;
    }
    int layer = (b < 452) ? 1 : 2;
    int t = (layer == 1) ? (b - 196) : (b - 452);
    const float* __restrict__ W = (layer == 1) ? W1 : W2;
    __nv_bfloat16* __restrict__ Wh = (layer == 1) ? g_W1h : g_W2h;
    __nv_bfloat16* __restrict__ Wl = (layer == 1) ? g_W1l : g_W2l;

    __shared__ float tt[32][33];
    int k0 = (t & 15) * 32, n0 = (t >> 4) * 32;
    int tx = tid & 31, ty = tid >> 5;
    for (int s = 0; s < 4; s++) {
        int j = ty + 8 * s;
        tt[j][tx] = W[(size_t)(k0 + j) * DD + n0 + tx];
    }
    __syncthreads();
    for (int s = 0; s < 4; s++) {
        int j = ty + 8 * s;
        float a = tt[tx][j];
        __nv_bfloat16 h = __float2bfloat16(a);
        float lo = a - __bfloat162float(h);
        Wh[(size_t)(n0 + j) * DD + k0 + tx] = h;
        Wl[(size_t)(n0 + j) * DD + k0 + tx] = __float2bfloat16(lo);
    }
}

// ---------------------------------------------------------------------------
// bf16x3 tensor-core GEMM: CTA tile 64x128, 8 warps (2m x 4n), warp tile 32x32,
// 2 CTAs/SM (launch_bounds reg cap), double-buffered smem, B via cp.async,
// fused aggregation epilogue: h = op(A)@W ; HS = h*dis ; dest = h*dis^2 + bias
// ---------------------------------------------------------------------------
template <bool A_BUFB, bool RELU, int LAYER>
__global__ __launch_bounds__(256, 2) void gemm_bf16x3(
    const float* __restrict__ Aext,
    const float* __restrict__ bias, float* __restrict__ dest_ext, int M)
{
    extern __shared__ __align__(16) char smem[];
    const float* __restrict__ A = A_BUFB ? (const float*)g_bufB : Aext;
    const __nv_bfloat16* __restrict__ Wh = (LAYER == 1) ? g_W1h : g_W2h;
    const __nv_bfloat16* __restrict__ Wl = (LAYER == 1) ? g_W1l : g_W2l;
    float* __restrict__ dest = A_BUFB ? dest_ext : (float*)g_bufB;
    float* __restrict__ HS = g_bufA;

    const uint32_t sb = smem_u32(smem);
    const int tid = threadIdx.x, lane = tid & 31, wid = tid >> 5;
    const int wm = (wid & 1) * 32;       // 2 warps in m
    const int wn = (wid >> 1) * 32;      // 4 warps in n
    const int bm = blockIdx.y * BM;
    const int n0 = blockIdx.x * BN;

    // A loader: 64 rows x 32 floats = 512 float4, 2/thread
    const int a_row = tid >> 3, a_c4 = tid & 7;          // +32 rows per r
    // B loader: 128 rows x 4 chunks16 = 512 chunks per buffer, 2/thread
    const int b_row = tid >> 2, b_c = tid & 3;           // +64 rows per r

    float4 pa[2];

    auto issue_B = [&](int k0, int st) {
        uint32_t bh = sb + st * STAGE + ST_BH;
        uint32_t bl = sb + st * STAGE + ST_BL;
#pragma unroll
        for (int r = 0; r < 2; r++) {
            int row = b_row + 64 * r;
            size_t g = (size_t)(n0 + row) * DD + k0 + b_c * 8;
            uint32_t so = (uint32_t)(row * SA + b_c * 8) * 2;
            CPASYNC16(bh + so, (const void*)&Wh[g]);
            CPASYNC16(bl + so, (const void*)&Wl[g]);
        }
        CPCOMMIT();
    };
    auto issue_A = [&](int k0) {
#pragma unroll
        for (int r = 0; r < 2; r++) {
            int row = a_row + 32 * r;
            int g = bm + row;
            float4 v = make_float4(0.f, 0.f, 0.f, 0.f);
            if (g < M) v = *(const float4*)&A[(size_t)g * DD + k0 + a_c4 * 4];
            pa[r] = v;
        }
    };
    auto commit_A = [&](int st) {
        uint32_t ah = sb + st * STAGE;
        uint32_t al = ah + ST_AL;
#pragma unroll
        for (int r = 0; r < 2; r++) {
            int row = a_row + 32 * r;
            float4 v = pa[r];
            if (RELU) {
                v.x = fmaxf(v.x, 0.f); v.y = fmaxf(v.y, 0.f);
                v.z = fmaxf(v.z, 0.f); v.w = fmaxf(v.w, 0.f);
            }
            __nv_bfloat16 hx = __float2bfloat16(v.x);
            __nv_bfloat16 hy = __float2bfloat16(v.y);
            __nv_bfloat16 hz = __float2bfloat16(v.z);
            __nv_bfloat16 hw = __float2bfloat16(v.w);
            __nv_bfloat16 lx = __float2bfloat16(v.x - __bfloat162float(hx));
            __nv_bfloat16 ly = __float2bfloat16(v.y - __bfloat162float(hy));
            __nv_bfloat16 lz = __float2bfloat16(v.z - __bfloat162float(hz));
            __nv_bfloat16 lw = __float2bfloat16(v.w - __bfloat162float(hw));
            uint32_t so = (uint32_t)(row * SA + a_c4 * 4) * 2;
            asm volatile("st.shared.v2.b32 [%0], {%1,%2};" ::
                "r"(ah + so), "r"(pack_bf16(hx, hy)), "r"(pack_bf16(hz, hw))
                : "memory");
            asm volatile("st.shared.v2.b32 [%0], {%1,%2};" ::
                "r"(al + so), "r"(pack_bf16(lx, ly)), "r"(pack_bf16(lz, lw))
                : "memory");
        }
    };

    float c[2][4][4];
#pragma unroll
    for (int i = 0; i < 2; i++)
#pragma unroll
        for (int j = 0; j < 4; j++)
#pragma unroll
            for (int q = 0; q < 4; q++) c[i][j][q] = 0.0f;

    // Prologue: fill stage 0
    issue_B(0, 0);
    issue_A(0);
    commit_A(0);
    CPWAIT0();
    __syncthreads();

    for (int it = 0; it < NIT; it++) {
        const int st = it & 1;
        const bool more = (it + 1 < NIT);
        if (more) {
            issue_B((it + 1) * BK, st ^ 1);
            issue_A((it + 1) * BK);
        }

        const uint32_t ahB = sb + st * STAGE;
        const uint32_t alB = ahB + ST_AL;
        const uint32_t bhB = sb + st * STAGE + ST_BH;
        const uint32_t blB = sb + st * STAGE + ST_BL;

#pragma unroll
        for (int ks = 0; ks < 2; ks++) {
            const int k0s = ks * 16;
            uint32_t ah[2][4], al[2][4];
#pragma unroll
            for (int mi = 0; mi < 2; mi++) {
                uint32_t off = (uint32_t)(((wm + mi * 16 + (lane & 15)) * SA
                                + k0s + 8 * (lane >> 4)) * 2);
                LDM4(ah[mi], ahB + off);
                LDM4(al[mi], alB + off);
            }
#pragma unroll
            for (int nj = 0; nj < 2; nj++) {          // 2 x n16 groups
                uint32_t bh[4], bl[4];
                uint32_t off = (uint32_t)(((wn + nj * 16 + (lane & 7)
                                + 8 * (lane >> 4)) * SA
                                + k0s + 8 * ((lane >> 3) & 1)) * 2);
                LDM4(bh, bhB + off);
                LDM4(bl, blB + off);
#pragma unroll
                for (int mi = 0; mi < 2; mi++) {
                    MMA(c[mi][nj * 2],     ah[mi], bh[0], bh[1]);
                    MMA(c[mi][nj * 2],     ah[mi], bl[0], bl[1]);
                    MMA(c[mi][nj * 2],     al[mi], bh[0], bh[1]);
                    MMA(c[mi][nj * 2 + 1], ah[mi], bh[2], bh[3]);
                    MMA(c[mi][nj * 2 + 1], ah[mi], bl[2], bl[3]);
                    MMA(c[mi][nj * 2 + 1], al[mi], bh[2], bh[3]);
                }
            }
        }
        if (more) {
            commit_A(st ^ 1);
            CPWAIT0();
        }
        __syncthreads();
    }

    // Fused epilogue: hs = h*dis, dest = h*dis^2 + bias
#pragma unroll
    for (int mi = 0; mi < 2; mi++) {
        int r0 = bm + wm + mi * 16 + (lane >> 2);
        int r1 = r0 + 8;
        float d0 = (r0 < M) ? g_dis[r0] : 0.f;
        float d1 = (r1 < M) ? g_dis[r1] : 0.f;
#pragma unroll
        for (int nj2 = 0; nj2 < 4; nj2++) {
            int col = n0 + wn + nj2 * 8 + (lane & 3) * 2;
            float2 bv = *(const float2*)&bias[col];
            if (r0 < M) {
                float h0 = c[mi][nj2][0] * d0, h1 = c[mi][nj2][1] * d0;
                *(float2*)&HS[(size_t)r0 * DD + col] = make_float2(h0, h1);
                *(float2*)&dest[(size_t)r0 * DD + col] =
                    make_float2(fmaf(h0, d0, bv.x), fmaf(h1, d0, bv.y));
            }
            if (r1 < M) {
                float h0 = c[mi][nj2][2] * d1, h1 = c[mi][nj2][3] * d1;
                *(float2*)&HS[(size_t)r1 * DD + col] = make_float2(h0, h1);
                *(float2*)&dest[(size_t)r1 * DD + col] =
                    make_float2(fmaf(h0, d1, bv.x), fmaf(h1, d1, bv.y));
            }
        }
    }
}

// ---------------------------------------------------------------------------
// Edge scatter: agg[dst,:] += dis[dst] * hs[src,:]
// ---------------------------------------------------------------------------
template <bool TO_BUFB>
__global__ __launch_bounds__(256) void edge_scatter_kernel(
    const void* __restrict__ ei, float* __restrict__ agg_ext)
{
    float* __restrict__ agg = TO_BUFB ? (float*)g_bufB : agg_ext;
    const float* __restrict__ hs = g_bufA;
    int warp = (blockIdx.x * blockDim.x + threadIdx.x) >> 5;
    int lane = threadIdx.x & 31;
    if (warp >= EE) return;
    int s = load_idx(ei, warp);
    int d = load_idx(ei, EE + warp);
    float w = g_dis[d];
    const float4* hr = (const float4*)(hs + (size_t)s * DD);
    float* ar = agg + (size_t)d * DD;
#pragma unroll
    for (int i = 0; i < 4; i++) {
        int c4 = lane + i * 32;
        float4 v = hr[c4];
        float* p = ar + c4 * 4;
        asm volatile("red.global.add.v4.f32 [%0], {%1,%2,%3,%4};"
                     :: "l"(p), "f"(v.x * w), "f"(v.y * w),
                        "f"(v.z * w), "f"(v.w * w) : "memory");
    }
}

// ---------------------------------------------------------------------------
// >48KB dynamic smem opt-in (non-stream API: capture-safe; also at static init)
// ---------------------------------------------------------------------------
static void set_smem_attrs() {
    cudaFuncSetAttribute(gemm_bf16x3<false, false, 1>,
                         cudaFuncAttributeMaxDynamicSharedMemorySize, SMEM_DYN);
    cudaFuncSetAttribute(gemm_bf16x3<true, true, 2>,
                         cudaFuncAttributeMaxDynamicSharedMemorySize, SMEM_DYN);
}
namespace { struct GInit { GInit() { set_smem_attrs(); } } g_init; }

// ---------------------------------------------------------------------------
// Launch (graph-capturable; launch #4 = gemm1 for ncu's profiled slot)
// ---------------------------------------------------------------------------
extern "C" void kernel_launch(void* const* d_in, const int* in_sizes, int n_in,
                              void* d_out, int out_size)
{
    const float* x  = (const float*)d_in[0];
    const void*  ei = d_in[1];
    const float* W1 = (const float*)d_in[2];
    const float* b1 = (const float*)d_in[3];
    const float* W2 = (const float*)d_in[4];
    const float* b2 = (const float*)d_in[5];
    float* out = (float*)d_out;

    set_smem_attrs();

    dim3 gemm_grid(DD / BN, (NN + BM - 1) / BM);   // (4, 782); x-major: same-bm adjacent
    const int edge_blocks = (EE + 7) / 8;

    k1_detect_initdeg<<<196, 256>>>((const unsigned int*)ei);              // #1
    k2_count_deg<<<(EE + 255) / 256, 256>>>(ei);                           // #2
    k3_dis_wsplit<<<708, 256>>>(W1, W2);                                   // #3

    gemm_bf16x3<false, false, 1><<<gemm_grid, 256, SMEM_DYN>>>(x, b1, nullptr, NN); // #4
    edge_scatter_kernel<true><<<edge_blocks, 256>>>(ei, nullptr);                   // #5

    gemm_bf16x3<true, true, 2><<<gemm_grid, 256, SMEM_DYN>>>(nullptr, b2, out, NN); // #6
    edge_scatter_kernel<false><<<edge_blocks, 256>>>(ei, out);                      // #7
}

// round 13
// speedup vs baseline: 2.2830x; 1.1353x over previous
#include <cuda_runtime.h>
#include <cuda_fp16.h>
#include <cstdint>

#define NN 50000
#define DD 512
#define EE 150000

#define BM 64
#define BN 128
#define BK 32
#define SA 40              // smem row stride in fp16 (80B rows -> conflict-free ldmatrix)
#define NIT (DD / BK)      // 16

// Stage layout (bytes): Ah 5120 | Bh 10240 | Bl 10240
#define ST_BH 5120
#define ST_BL 15360
#define STAGE 25600
#define SMEM_DYN (2 * STAGE)   // 51200 per CTA; 2 CTAs/SM = 102400

// ---------------------------------------------------------------------------
// Device globals (no allocation anywhere)
// ---------------------------------------------------------------------------
__device__ __align__(16) float g_bufA[(size_t)NN * DD];   // scaled messages hs
__device__ __align__(16) float g_bufB[(size_t)NN * DD];   // layer-1 aggregate
__device__ __align__(16) __half g_W1h[DD * DD], g_W1l[DD * DD];
__device__ __align__(16) __half g_W2h[DD * DD], g_W2l[DD * DD];
__device__ float g_deg[NN];
__device__ float g_dis[NN];
__device__ int   g_is64;

// ---------------------------------------------------------------------------
// PTX helpers (ldmatrix / mma.sync / cp.async are sm_80+, legal on plain sm_103)
// ---------------------------------------------------------------------------
__device__ __forceinline__ uint32_t smem_u32(const void* p) {
    uint32_t a;
    asm("{ .reg .u64 t; cvta.to.shared.u64 t, %1; cvt.u32.u64 %0, t; }"
        : "=r"(a) : "l"(p));
    return a;
}
#define LDM4(d, addr)                                                           \
    asm volatile("ldmatrix.sync.aligned.m8n8.x4.shared.b16 {%0,%1,%2,%3}, [%4];"\
        : "=r"((d)[0]), "=r"((d)[1]), "=r"((d)[2]), "=r"((d)[3]) : "r"(addr))
#define MMA(cc, aa, b0, b1)                                                     \
    asm volatile("mma.sync.aligned.m16n8k16.row.col.f32.f16.f16.f32 "           \
        "{%0,%1,%2,%3}, {%4,%5,%6,%7}, {%8,%9}, {%0,%1,%2,%3};"                 \
        : "+f"((cc)[0]), "+f"((cc)[1]), "+f"((cc)[2]), "+f"((cc)[3])            \
        : "r"((aa)[0]), "r"((aa)[1]), "r"((aa)[2]), "r"((aa)[3]),               \
          "r"(b0), "r"(b1))
#define CPASYNC16(sm, gm)                                                       \
    asm volatile("cp.async.cg.shared.global [%0], [%1], 16;"                    \
                 :: "r"(sm), "l"(gm) : "memory")
#define CPCOMMIT()  asm volatile("cp.async.commit_group;" ::: "memory")
#define CPWAIT0()   asm volatile("cp.async.wait_group 0;" ::: "memory")

__device__ __forceinline__ uint32_t pack_h2(float a, float b) {
    __half2 t = __floats2half2_rn(a, b);        // x = low half
    return *reinterpret_cast<uint32_t*>(&t);
}
__device__ __forceinline__ int load_idx(const void* __restrict__ ei, int pos) {
    if (g_is64) return (int)((const long long*)ei)[pos];
    return ((const int*)ei)[pos];
}

// ---------------------------------------------------------------------------
// k1: dtype detect (block 0) + deg init
// ---------------------------------------------------------------------------
__global__ void k1_detect_initdeg(const unsigned int* __restrict__ w) {
    if (blockIdx.x == 0 && threadIdx.x == 0) {
        int is64 = 1;
        for (int i = 0; i < 128; i++)
            if (w[2 * i + 1] != 0u) { is64 = 0; break; }
        g_is64 = is64;
    }
    int i = blockIdx.x * blockDim.x + threadIdx.x;
    if (i < NN) g_deg[i] = 1.0f;
}

__global__ void k2_count_deg(const void* __restrict__ ei) {
    int e = blockIdx.x * blockDim.x + threadIdx.x;
    if (e < EE) atomicAdd(&g_deg[load_idx(ei, EE + e)], 1.0f);
}

// ---------------------------------------------------------------------------
// k3: calc_dis ([0,196)) + W1 split ([196,452)) + W2 split ([452,708))
//     Wh[n][k] = fp16(W[k][n]), Wl = fp16(residual)  (residual may be denormal
//     in fp16 — HMMA treats fp16 operands exactly, and even if flushed the
//     scheme degrades to ~3.5e-4, still under threshold)
// ---------------------------------------------------------------------------
__global__ void k3_dis_wsplit(const float* __restrict__ W1,
                              const float* __restrict__ W2)
{
    int b = blockIdx.x;
    int tid = threadIdx.x;
    if (b < 196) {
        int i = b * 256 + tid;
        if (i < NN) g_dis[i] = rsqrtf(g_deg[i]);
        return;
    }
    int layer = (b < 452) ? 1 : 2;
    int t = (layer == 1) ? (b - 196) : (b - 452);
    const float* __restrict__ W = (layer == 1) ? W1 : W2;
    __half* __restrict__ Wh = (layer == 1) ? g_W1h : g_W2h;
    __half* __restrict__ Wl = (layer == 1) ? g_W1l : g_W2l;

    __shared__ float tt[32][33];
    int k0 = (t & 15) * 32, n0 = (t >> 4) * 32;
    int tx = tid & 31, ty = tid >> 5;
    for (int s = 0; s < 4; s++) {
        int j = ty + 8 * s;
        tt[j][tx] = W[(size_t)(k0 + j) * DD + n0 + tx];
    }
    __syncthreads();
    for (int s = 0; s < 4; s++) {
        int j = ty + 8 * s;
        float a = tt[tx][j];
        __half h = __float2half_rn(a);
        float lo = a - __half2float(h);
        Wh[(size_t)(n0 + j) * DD + k0 + tx] = h;
        Wl[(size_t)(n0 + j) * DD + k0 + tx] = __float2half_rn(lo);
    }
}

// ---------------------------------------------------------------------------
// fp16 2-term tensor-core GEMM: CTA 64x128, 8 warps (2m x 4n), warp tile 32x32,
// 2 CTAs/SM, double-buffered smem, B via cp.async.
//   h = op(A)@W  with  D = Ah*Bh + Ah*Bl   (A single fp16, B split fp16)
// Fused aggregation epilogue: HS = h*dis ; dest = h*dis^2 + bias
// ---------------------------------------------------------------------------
template <bool A_BUFB, bool RELU, int LAYER>
__global__ __launch_bounds__(256, 2) void gemm_f16x2(
    const float* __restrict__ Aext,
    const float* __restrict__ bias, float* __restrict__ dest_ext, int M)
{
    extern __shared__ __align__(16) char smem[];
    const float* __restrict__ A = A_BUFB ? (const float*)g_bufB : Aext;
    const __half* __restrict__ Wh = (LAYER == 1) ? g_W1h : g_W2h;
    const __half* __restrict__ Wl = (LAYER == 1) ? g_W1l : g_W2l;
    float* __restrict__ dest = A_BUFB ? dest_ext : (float*)g_bufB;
    float* __restrict__ HS = g_bufA;

    const uint32_t sb = smem_u32(smem);
    const int tid = threadIdx.x, lane = tid & 31, wid = tid >> 5;
    const int wm = (wid & 1) * 32;       // 2 warps in m
    const int wn = (wid >> 1) * 32;      // 4 warps in n
    const int bm = blockIdx.y * BM;
    const int n0 = blockIdx.x * BN;

    // A loader: 64 rows x 32 floats = 512 float4, 2/thread
    const int a_row = tid >> 3, a_c4 = tid & 7;          // +32 rows per r
    // B loader: 128 rows x 4 chunks16 per buffer, 2/thread
    const int b_row = tid >> 2, b_c = tid & 3;           // +64 rows per r

    float4 pa[2];

    auto issue_B = [&](int k0, int st) {
        uint32_t bh = sb + st * STAGE + ST_BH;
        uint32_t bl = sb + st * STAGE + ST_BL;
#pragma unroll
        for (int r = 0; r < 2; r++) {
            int row = b_row + 64 * r;
            size_t g = (size_t)(n0 + row) * DD + k0 + b_c * 8;
            uint32_t so = (uint32_t)(row * SA + b_c * 8) * 2;
            CPASYNC16(bh + so, (const void*)&Wh[g]);
            CPASYNC16(bl + so, (const void*)&Wl[g]);
        }
        CPCOMMIT();
    };
    auto issue_A = [&](int k0) {
#pragma unroll
        for (int r = 0; r < 2; r++) {
            int row = a_row + 32 * r;
            int g = bm + row;
            float4 v = make_float4(0.f, 0.f, 0.f, 0.f);
            if (g < M) v = *(const float4*)&A[(size_t)g * DD + k0 + a_c4 * 4];
            pa[r] = v;
        }
    };
    auto commit_A = [&](int st) {
        uint32_t ah = sb + st * STAGE;
#pragma unroll
        for (int r = 0; r < 2; r++) {
            int row = a_row + 32 * r;
            float4 v = pa[r];
            if (RELU) {
                v.x = fmaxf(v.x, 0.f); v.y = fmaxf(v.y, 0.f);
                v.z = fmaxf(v.z, 0.f); v.w = fmaxf(v.w, 0.f);
            }
            uint32_t so = (uint32_t)(row * SA + a_c4 * 4) * 2;
            asm volatile("st.shared.v2.b32 [%0], {%1,%2};" ::
                "r"(ah + so), "r"(pack_h2(v.x, v.y)), "r"(pack_h2(v.z, v.w))
                : "memory");
        }
    };

    float c[2][4][4];
#pragma unroll
    for (int i = 0; i < 2; i++)
#pragma unroll
        for (int j = 0; j < 4; j++)
#pragma unroll
            for (int q = 0; q < 4; q++) c[i][j][q] = 0.0f;

    // Prologue: fill stage 0
    issue_B(0, 0);
    issue_A(0);
    commit_A(0);
    CPWAIT0();
    __syncthreads();

    for (int it = 0; it < NIT; it++) {
        const int st = it & 1;
        const bool more = (it + 1 < NIT);
        if (more) {
            issue_B((it + 1) * BK, st ^ 1);
            issue_A((it + 1) * BK);
        }

        const uint32_t ahB = sb + st * STAGE;
        const uint32_t bhB = sb + st * STAGE + ST_BH;
        const uint32_t blB = sb + st * STAGE + ST_BL;

#pragma unroll
        for (int ks = 0; ks < 2; ks++) {
            const int k0s = ks * 16;
            uint32_t ah[2][4];
#pragma unroll
            for (int mi = 0; mi < 2; mi++) {
                uint32_t off = (uint32_t)(((wm + mi * 16 + (lane & 15)) * SA
                                + k0s + 8 * (lane >> 4)) * 2);
                LDM4(ah[mi], ahB + off);
            }
#pragma unroll
            for (int nj = 0; nj < 2; nj++) {          // 2 x n16 groups
                uint32_t bh[4], bl[4];
                uint32_t off = (uint32_t)(((wn + nj * 16 + (lane & 7)
                                + 8 * (lane >> 4)) * SA
                                + k0s + 8 * ((lane >> 3) & 1)) * 2);
                LDM4(bh, bhB + off);
                LDM4(bl, blB + off);
#pragma unroll
                for (int mi = 0; mi < 2; mi++) {
                    MMA(c[mi][nj * 2],     ah[mi], bh[0], bh[1]);
                    MMA(c[mi][nj * 2],     ah[mi], bl[0], bl[1]);
                    MMA(c[mi][nj * 2 + 1], ah[mi], bh[2], bh[3]);
                    MMA(c[mi][nj * 2 + 1], ah[mi], bl[2], bl[3]);
                }
            }
        }
        if (more) {
            commit_A(st ^ 1);
            CPWAIT0();
        }
        __syncthreads();
    }

    // Fused epilogue: hs = h*dis, dest = h*dis^2 + bias
#pragma unroll
    for (int mi = 0; mi < 2; mi++) {
        int r0 = bm + wm + mi * 16 + (lane >> 2);
        int r1 = r0 + 8;
        float d0 = (r0 < M) ? g_dis[r0] : 0.f;
        float d1 = (r1 < M) ? g_dis[r1] : 0.f;
#pragma unroll
        for (int nj2 = 0; nj2 < 4; nj2++) {
            int col = n0 + wn + nj2 * 8 + (lane & 3) * 2;
            float2 bv = *(const float2*)&bias[col];
            if (r0 < M) {
                float h0 = c[mi][nj2][0] * d0, h1 = c[mi][nj2][1] * d0;
                *(float2*)&HS[(size_t)r0 * DD + col] = make_float2(h0, h1);
                *(float2*)&dest[(size_t)r0 * DD + col] =
                    make_float2(fmaf(h0, d0, bv.x), fmaf(h1, d0, bv.y));
            }
            if (r1 < M) {
                float h0 = c[mi][nj2][2] * d1, h1 = c[mi][nj2][3] * d1;
                *(float2*)&HS[(size_t)r1 * DD + col] = make_float2(h0, h1);
                *(float2*)&dest[(size_t)r1 * DD + col] =
                    make_float2(fmaf(h0, d1, bv.x), fmaf(h1, d1, bv.y));
            }
        }
    }
}

// ---------------------------------------------------------------------------
// Edge scatter: agg[dst,:] += dis[dst] * hs[src,:]
// ---------------------------------------------------------------------------
template <bool TO_BUFB>
__global__ __launch_bounds__(256) void edge_scatter_kernel(
    const void* __restrict__ ei, float* __restrict__ agg_ext)
{
    float* __restrict__ agg = TO_BUFB ? (float*)g_bufB : agg_ext;
    const float* __restrict__ hs = g_bufA;
    int warp = (blockIdx.x * blockDim.x + threadIdx.x) >> 5;
    int lane = threadIdx.x & 31;
    if (warp >= EE) return;
    int s = load_idx(ei, warp);
    int d = load_idx(ei, EE + warp);
    float w = g_dis[d];
    const float4* hr = (const float4*)(hs + (size_t)s * DD);
    float* ar = agg + (size_t)d * DD;
#pragma unroll
    for (int i = 0; i < 4; i++) {
        int c4 = lane + i * 32;
        float4 v = hr[c4];
        float* p = ar + c4 * 4;
        asm volatile("red.global.add.v4.f32 [%0], {%1,%2,%3,%4};"
                     :: "l"(p), "f"(v.x * w), "f"(v.y * w),
                        "f"(v.z * w), "f"(v.w * w) : "memory");
    }
}

// ---------------------------------------------------------------------------
// >48KB dynamic smem opt-in (non-stream API: capture-safe; also at static init)
// ---------------------------------------------------------------------------
static void set_smem_attrs() {
    cudaFuncSetAttribute(gemm_f16x2<false, false, 1>,
                         cudaFuncAttributeMaxDynamicSharedMemorySize, SMEM_DYN);
    cudaFuncSetAttribute(gemm_f16x2<true, true, 2>,
                         cudaFuncAttributeMaxDynamicSharedMemorySize, SMEM_DYN);
}
namespace { struct GInit { GInit() { set_smem_attrs(); } } g_init; }

// ---------------------------------------------------------------------------
// Launch (graph-capturable; launch #4 = gemm1 for ncu's profiled slot)
// ---------------------------------------------------------------------------
extern "C" void kernel_launch(void* const* d_in, const int* in_sizes, int n_in,
                              void* d_out, int out_size)
{
    const float* x  = (const float*)d_in[0];
    const void*  ei = d_in[1];
    const float* W1 = (const float*)d_in[2];
    const float* b1 = (const float*)d_in[3];
    const float* W2 = (const float*)d_in[4];
    const float* b2 = (const float*)d_in[5];
    float* out = (float*)d_out;

    set_smem_attrs();

    dim3 gemm_grid(DD / BN, (NN + BM - 1) / BM);   // (4, 782); x-major: same-bm adjacent
    const int edge_blocks = (EE + 7) / 8;

    k1_detect_initdeg<<<196, 256>>>((const unsigned int*)ei);              // #1
    k2_count_deg<<<(EE + 255) / 256, 256>>>(ei);                           // #2
    k3_dis_wsplit<<<708, 256>>>(W1, W2);                                   // #3

    gemm_f16x2<false, false, 1><<<gemm_grid, 256, SMEM_DYN>>>(x, b1, nullptr, NN); // #4
    edge_scatter_kernel<true><<<edge_blocks, 256>>>(ei, nullptr);                  // #5

    gemm_f16x2<true, true, 2><<<gemm_grid, 256, SMEM_DYN>>>(nullptr, b2, out, NN); // #6
    edge_scatter_kernel<false><<<edge_blocks, 256>>>(ei, out);                     // #7
}

// round 14
// speedup vs baseline: 2.5226x; 1.1049x over previous
#include <cuda_runtime.h>
#include <cuda_fp16.h>
#include <cstdint>

#define NN 50000
#define DD 512
#define EE 150000

#define BM 64
#define BN 128
#define BK 64
#define SA 72              // smem row stride in fp16 (144B rows -> conflict-free ldmatrix)
#define NIT (DD / BK)      // 8

// Stage layout (bytes): Ah 9216 | Bh 18432 | Bl 18432
#define ST_BH 9216
#define ST_BL 27648
#define STAGE 46080
#define SMEM_DYN (2 * STAGE)   // 92160 per CTA; 2 CTAs/SM = 184320 (< 228KB)

// ---------------------------------------------------------------------------
// Device globals (no allocation anywhere)
// ---------------------------------------------------------------------------
__device__ __align__(16) float g_bufA[(size_t)NN * DD];   // scaled messages hs
__device__ __align__(16) float g_bufB[(size_t)NN * DD];   // layer-1 aggregate
__device__ __align__(16) __half g_W1h[DD * DD], g_W1l[DD * DD];
__device__ __align__(16) __half g_W2h[DD * DD], g_W2l[DD * DD];
__device__ float g_deg[NN];
__device__ float g_dis[NN];
__device__ int   g_is64;

// ---------------------------------------------------------------------------
// PTX helpers (ldmatrix / mma.sync / cp.async are sm_80+, legal on plain sm_103)
// ---------------------------------------------------------------------------
__device__ __forceinline__ uint32_t smem_u32(const void* p) {
    uint32_t a;
    asm("{ .reg .u64 t; cvta.to.shared.u64 t, %1; cvt.u32.u64 %0, t; }"
        : "=r"(a) : "l"(p));
    return a;
}
#define LDM4(d, addr)                                                           \
    asm volatile("ldmatrix.sync.aligned.m8n8.x4.shared.b16 {%0,%1,%2,%3}, [%4];"\
        : "=r"((d)[0]), "=r"((d)[1]), "=r"((d)[2]), "=r"((d)[3]) : "r"(addr))
#define MMA(cc, aa, b0, b1)                                                     \
    asm volatile("mma.sync.aligned.m16n8k16.row.col.f32.f16.f16.f32 "           \
        "{%0,%1,%2,%3}, {%4,%5,%6,%7}, {%8,%9}, {%0,%1,%2,%3};"                 \
        : "+f"((cc)[0]), "+f"((cc)[1]), "+f"((cc)[2]), "+f"((cc)[3])            \
        : "r"((aa)[0]), "r"((aa)[1]), "r"((aa)[2]), "r"((aa)[3]),               \
          "r"(b0), "r"(b1))
#define CPASYNC16(sm, gm)                                                       \
    asm volatile("cp.async.cg.shared.global [%0], [%1], 16;"                    \
                 :: "r"(sm), "l"(gm) : "memory")
#define CPCOMMIT()  asm volatile("cp.async.commit_group;" ::: "memory")
#define CPWAIT0()   asm volatile("cp.async.wait_group 0;" ::: "memory")

__device__ __forceinline__ uint32_t pack_h2(float a, float b) {
    __half2 t = __floats2half2_rn(a, b);        // x = low half
    return *reinterpret_cast<uint32_t*>(&t);
}
__device__ __forceinline__ int load_idx(const void* __restrict__ ei, int pos) {
    if (g_is64) return (int)((const long long*)ei)[pos];
    return ((const int*)ei)[pos];
}

// ---------------------------------------------------------------------------
// k1: dtype detect (block 0) + deg init
// ---------------------------------------------------------------------------
__global__ void k1_detect_initdeg(const unsigned int* __restrict__ w) {
    if (blockIdx.x == 0 && threadIdx.x == 0) {
        int is64 = 1;
        for (int i = 0; i < 128; i++)
            if (w[2 * i + 1] != 0u) { is64 = 0; break; }
        g_is64 = is64;
    }
    int i = blockIdx.x * blockDim.x + threadIdx.x;
    if (i < NN) g_deg[i] = 1.0f;
}

__global__ void k2_count_deg(const void* __restrict__ ei) {
    int e = blockIdx.x * blockDim.x + threadIdx.x;
    if (e < EE) atomicAdd(&g_deg[load_idx(ei, EE + e)], 1.0f);
}

// ---------------------------------------------------------------------------
// k3: calc_dis ([0,196)) + W1 split ([196,452)) + W2 split ([452,708))
//     Wh[n][k] = fp16(W[k][n]), Wl = fp16(residual)
// ---------------------------------------------------------------------------
__global__ void k3_dis_wsplit(const float* __restrict__ W1,
                              const float* __restrict__ W2)
{
    int b = blockIdx.x;
    int tid = threadIdx.x;
    if (b < 196) {
        int i = b * 256 + tid;
        if (i < NN) g_dis[i] = rsqrtf(g_deg[i]);
        return;
    }
    int layer = (b < 452) ? 1 : 2;
    int t = (layer == 1) ? (b - 196) : (b - 452);
    const float* __restrict__ W = (layer == 1) ? W1 : W2;
    __half* __restrict__ Wh = (layer == 1) ? g_W1h : g_W2h;
    __half* __restrict__ Wl = (layer == 1) ? g_W1l : g_W2l;

    __shared__ float tt[32][33];
    int k0 = (t & 15) * 32, n0 = (t >> 4) * 32;
    int tx = tid & 31, ty = tid >> 5;
    for (int s = 0; s < 4; s++) {
        int j = ty + 8 * s;
        tt[j][tx] = W[(size_t)(k0 + j) * DD + n0 + tx];
    }
    __syncthreads();
    for (int s = 0; s < 4; s++) {
        int j = ty + 8 * s;
        float a = tt[tx][j];
        __half h = __float2half_rn(a);
        float lo = a - __half2float(h);
        Wh[(size_t)(n0 + j) * DD + k0 + tx] = h;
        Wl[(size_t)(n0 + j) * DD + k0 + tx] = __float2half_rn(lo);
    }
}

// ---------------------------------------------------------------------------
// fp16 2-term GEMM: CTA 64x128, 8 warps (2m x 4n), warp tile 32x32, BK=64,
// 2 CTAs/SM, double-buffered smem + double-buffered ldmatrix fragments.
//   h = op(A)@W  with  D = Ah*Bh + Ah*Bl
// Fused aggregation epilogue: HS = h*dis ; dest = h*dis^2 + bias
// ---------------------------------------------------------------------------
template <bool A_BUFB, bool RELU, int LAYER>
__global__ __launch_bounds__(256, 2) void gemm_f16x2(
    const float* __restrict__ Aext,
    const float* __restrict__ bias, float* __restrict__ dest_ext, int M)
{
    extern __shared__ __align__(16) char smem[];
    const float* __restrict__ A = A_BUFB ? (const float*)g_bufB : Aext;
    const __half* __restrict__ Wh = (LAYER == 1) ? g_W1h : g_W2h;
    const __half* __restrict__ Wl = (LAYER == 1) ? g_W1l : g_W2l;
    float* __restrict__ dest = A_BUFB ? dest_ext : (float*)g_bufB;
    float* __restrict__ HS = g_bufA;

    const uint32_t sb = smem_u32(smem);
    const int tid = threadIdx.x, lane = tid & 31, wid = tid >> 5;
    const int wm = (wid & 1) * 32;       // 2 warps in m
    const int wn = (wid >> 1) * 32;      // 4 warps in n
    const int bm = blockIdx.y * BM;
    const int n0 = blockIdx.x * BN;

    // A loader: 64 rows x 64 floats = 1024 float4, 4/thread
    const int a_row = tid >> 4, a_c4 = tid & 15;         // +16 rows per r
    // B loader: 128 rows x 8 chunks16 per buffer = 1024, 4/thread (x hi/lo)
    const int b_row = tid >> 3, b_c = tid & 7;           // +32 rows per r

    float4 pa[4];

    auto issue_B = [&](int k0, int st) {
        uint32_t bh = sb + st * STAGE + ST_BH;
        uint32_t bl = sb + st * STAGE + ST_BL;
#pragma unroll
        for (int r = 0; r < 4; r++) {
            int row = b_row + 32 * r;
            size_t g = (size_t)(n0 + row) * DD + k0 + b_c * 8;
            uint32_t so = (uint32_t)(row * SA + b_c * 8) * 2;
            CPASYNC16(bh + so, (const void*)&Wh[g]);
            CPASYNC16(bl + so, (const void*)&Wl[g]);
        }
        CPCOMMIT();
    };
    auto issue_A = [&](int k0) {
#pragma unroll
        for (int r = 0; r < 4; r++) {
            int row = a_row + 16 * r;
            int g = bm + row;
            float4 v = make_float4(0.f, 0.f, 0.f, 0.f);
            if (g < M) v = *(const float4*)&A[(size_t)g * DD + k0 + a_c4 * 4];
            pa[r] = v;
        }
    };
    auto commit_A = [&](int st) {
        uint32_t ah = sb + st * STAGE;
#pragma unroll
        for (int r = 0; r < 4; r++) {
            int row = a_row + 16 * r;
            float4 v = pa[r];
            if (RELU) {
                v.x = fmaxf(v.x, 0.f); v.y = fmaxf(v.y, 0.f);
                v.z = fmaxf(v.z, 0.f); v.w = fmaxf(v.w, 0.f);
            }
            uint32_t so = (uint32_t)(row * SA + a_c4 * 4) * 2;
            asm volatile("st.shared.v2.b32 [%0], {%1,%2};" ::
                "r"(ah + so), "r"(pack_h2(v.x, v.y)), "r"(pack_h2(v.z, v.w))
                : "memory");
        }
    };

    // Fragment double buffers
    uint32_t ahf[2][2][4];            // [buf][mi][reg]
    uint32_t bhf[2][2][4], blf[2][2][4];  // [buf][nj][reg]

    // per-thread ldmatrix base offsets (k0s added per step)
    const uint32_t aoff0 = (uint32_t)(((wm + (lane & 15)) * SA
                          + 8 * (lane >> 4)) * 2);
    const uint32_t boff0 = (uint32_t)(((wn + (lane & 7) + 8 * (lane >> 4)) * SA
                          + 8 * ((lane >> 3) & 1)) * 2);

    auto load_frags = [&](int buf, uint32_t stBase, int k0s) {
        uint32_t aB = stBase + aoff0 + (uint32_t)(k0s * 2);
        uint32_t bhB = stBase + ST_BH + boff0 + (uint32_t)(k0s * 2);
        uint32_t blB = stBase + ST_BL + boff0 + (uint32_t)(k0s * 2);
#pragma unroll
        for (int mi = 0; mi < 2; mi++)
            LDM4(ahf[buf][mi], aB + (uint32_t)(mi * 16 * SA * 2));
#pragma unroll
        for (int nj = 0; nj < 2; nj++) {
            LDM4(bhf[buf][nj], bhB + (uint32_t)(nj * 16 * SA * 2));
            LDM4(blf[buf][nj], blB + (uint32_t)(nj * 16 * SA * 2));
        }
    };

    float c[2][4][4];
#pragma unroll
    for (int i = 0; i < 2; i++)
#pragma unroll
        for (int j = 0; j < 4; j++)
#pragma unroll
            for (int q = 0; q < 4; q++) c[i][j][q] = 0.0f;

    auto do_mma = [&](int buf) {
#pragma unroll
        for (int nj = 0; nj < 2; nj++)
#pragma unroll
            for (int mi = 0; mi < 2; mi++) {
                MMA(c[mi][nj * 2],     ahf[buf][mi], bhf[buf][nj][0], bhf[buf][nj][1]);
                MMA(c[mi][nj * 2],     ahf[buf][mi], blf[buf][nj][0], blf[buf][nj][1]);
                MMA(c[mi][nj * 2 + 1], ahf[buf][mi], bhf[buf][nj][2], bhf[buf][nj][3]);
                MMA(c[mi][nj * 2 + 1], ahf[buf][mi], blf[buf][nj][2], blf[buf][nj][3]);
            }
    };

    // Prologue: fill stage 0
    issue_B(0, 0);
    issue_A(0);
    commit_A(0);
    CPWAIT0();
    __syncthreads();

    for (int it = 0; it < NIT; it++) {
        const int st = it & 1;
        const bool more = (it + 1 < NIT);
        if (more) {
            issue_B((it + 1) * BK, st ^ 1);
            issue_A((it + 1) * BK);
        }
        const uint32_t stBase = sb + st * STAGE;

        load_frags(0, stBase, 0);
#pragma unroll
        for (int ks = 0; ks < 4; ks++) {
            if (ks < 3) load_frags((ks + 1) & 1, stBase, (ks + 1) * 16);
            do_mma(ks & 1);
        }

        if (more) {
            commit_A(st ^ 1);
            CPWAIT0();
        }
        __syncthreads();
    }

    // Fused epilogue: hs = h*dis, dest = h*dis^2 + bias
#pragma unroll
    for (int mi = 0; mi < 2; mi++) {
        int r0 = bm + wm + mi * 16 + (lane >> 2);
        int r1 = r0 + 8;
        float d0 = (r0 < M) ? g_dis[r0] : 0.f;
        float d1 = (r1 < M) ? g_dis[r1] : 0.f;
#pragma unroll
        for (int nj2 = 0; nj2 < 4; nj2++) {
            int col = n0 + wn + nj2 * 8 + (lane & 3) * 2;
            float2 bv = *(const float2*)&bias[col];
            if (r0 < M) {
                float h0 = c[mi][nj2][0] * d0, h1 = c[mi][nj2][1] * d0;
                *(float2*)&HS[(size_t)r0 * DD + col] = make_float2(h0, h1);
                *(float2*)&dest[(size_t)r0 * DD + col] =
                    make_float2(fmaf(h0, d0, bv.x), fmaf(h1, d0, bv.y));
            }
            if (r1 < M) {
                float h0 = c[mi][nj2][2] * d1, h1 = c[mi][nj2][3] * d1;
                *(float2*)&HS[(size_t)r1 * DD + col] = make_float2(h0, h1);
                *(float2*)&dest[(size_t)r1 * DD + col] =
                    make_float2(fmaf(h0, d1, bv.x), fmaf(h1, d1, bv.y));
            }
        }
    }
}

// ---------------------------------------------------------------------------
// Edge scatter: agg[dst,:] += dis[dst] * hs[src,:]
// ---------------------------------------------------------------------------
template <bool TO_BUFB>
__global__ __launch_bounds__(256) void edge_scatter_kernel(
    const void* __restrict__ ei, float* __restrict__ agg_ext)
{
    float* __restrict__ agg = TO_BUFB ? (float*)g_bufB : agg_ext;
    const float* __restrict__ hs = g_bufA;
    int warp = (blockIdx.x * blockDim.x + threadIdx.x) >> 5;
    int lane = threadIdx.x & 31;
    if (warp >= EE) return;
    int s = load_idx(ei, warp);
    int d = load_idx(ei, EE + warp);
    float w = g_dis[d];
    const float4* hr = (const float4*)(hs + (size_t)s * DD);
    float* ar = agg + (size_t)d * DD;
#pragma unroll
    for (int i = 0; i < 4; i++) {
        int c4 = lane + i * 32;
        float4 v = hr[c4];
        float* p = ar + c4 * 4;
        asm volatile("red.global.add.v4.f32 [%0], {%1,%2,%3,%4};"
                     :: "l"(p), "f"(v.x * w), "f"(v.y * w),
                        "f"(v.z * w), "f"(v.w * w) : "memory");
    }
}

// ---------------------------------------------------------------------------
// >48KB dynamic smem opt-in (non-stream API: capture-safe; also at static init)
// ---------------------------------------------------------------------------
static void set_smem_attrs() {
    cudaFuncSetAttribute(gemm_f16x2<false, false, 1>,
                         cudaFuncAttributeMaxDynamicSharedMemorySize, SMEM_DYN);
    cudaFuncSetAttribute(gemm_f16x2<true, true, 2>,
                         cudaFuncAttributeMaxDynamicSharedMemorySize, SMEM_DYN);
}
namespace { struct GInit { GInit() { set_smem_attrs(); } } g_init; }

// ---------------------------------------------------------------------------
// Launch (graph-capturable; launch #4 = gemm1 for ncu's profiled slot)
// ---------------------------------------------------------------------------
extern "C" void kernel_launch(void* const* d_in, const int* in_sizes, int n_in,
                              void* d_out, int out_size)
{
    const float* x  = (const float*)d_in[0];
    const void*  ei = d_in[1];
    const float* W1 = (const float*)d_in[2];
    const float* b1 = (const float*)d_in[3];
    const float* W2 = (const float*)d_in[4];
    const float* b2 = (const float*)d_in[5];
    float* out = (float*)d_out;

    set_smem_attrs();

    dim3 gemm_grid(DD / BN, (NN + BM - 1) / BM);   // (4, 782); x-major: same-bm adjacent
    const int edge_blocks = (EE + 7) / 8;

    k1_detect_initdeg<<<196, 256>>>((const unsigned int*)ei);              // #1
    k2_count_deg<<<(EE + 255) / 256, 256>>>(ei);                           // #2
    k3_dis_wsplit<<<708, 256>>>(W1, W2);                                   // #3

    gemm_f16x2<false, false, 1><<<gemm_grid, 256, SMEM_DYN>>>(x, b1, nullptr, NN); // #4
    edge_scatter_kernel<true><<<edge_blocks, 256>>>(ei, nullptr);                  // #5

    gemm_f16x2<true, true, 2><<<gemm_grid, 256, SMEM_DYN>>>(nullptr, b2, out, NN); // #6
    edge_scatter_kernel<false><<<edge_blocks, 256>>>(ei, out);                     // #7
}

// round 15
// speedup vs baseline: 3.0897x; 1.2248x over previous
#include <cuda_runtime.h>
#include <cuda_fp16.h>
#include <cstdint>

#define NN 50000
#define DD 512
#define EE 150000

#define BM 64
#define BN 128
#define BK 64
#define SA 72              // smem row stride in fp16 (144B rows -> conflict-free ldmatrix)
#define NIT (DD / BK)      // 8

// Stage layout (bytes): Ah 9216 | Bh 18432
#define ST_BH 9216
#define STAGE 27648
#define SMEM_DYN (2 * STAGE)   // 55296 per CTA; 2 CTAs/SM = 110592

// ---------------------------------------------------------------------------
// Device globals (no allocation anywhere)
// ---------------------------------------------------------------------------
__device__ __align__(16) float g_bufA[(size_t)NN * DD];   // scaled messages hs
__device__ __align__(16) float g_bufB[(size_t)NN * DD];   // layer-1 aggregate
__device__ __align__(16) __half g_W1h[DD * DD];
__device__ __align__(16) __half g_W2h[DD * DD];
__device__ float g_deg[NN];
__device__ float g_dis[NN];
__device__ int   g_is64;

// ---------------------------------------------------------------------------
// PTX helpers (ldmatrix / mma.sync / cp.async are sm_80+, legal on plain sm_103)
// ---------------------------------------------------------------------------
__device__ __forceinline__ uint32_t smem_u32(const void* p) {
    uint32_t a;
    asm("{ .reg .u64 t; cvta.to.shared.u64 t, %1; cvt.u32.u64 %0, t; }"
        : "=r"(a) : "l"(p));
    return a;
}
#define LDM4(d, addr)                                                           \
    asm volatile("ldmatrix.sync.aligned.m8n8.x4.shared.b16 {%0,%1,%2,%3}, [%4];"\
        : "=r"((d)[0]), "=r"((d)[1]), "=r"((d)[2]), "=r"((d)[3]) : "r"(addr))
#define MMA(cc, aa, b0, b1)                                                     \
    asm volatile("mma.sync.aligned.m16n8k16.row.col.f32.f16.f16.f32 "           \
        "{%0,%1,%2,%3}, {%4,%5,%6,%7}, {%8,%9}, {%0,%1,%2,%3};"                 \
        : "+f"((cc)[0]), "+f"((cc)[1]), "+f"((cc)[2]), "+f"((cc)[3])            \
        : "r"((aa)[0]), "r"((aa)[1]), "r"((aa)[2]), "r"((aa)[3]),               \
          "r"(b0), "r"(b1))
#define CPASYNC16(sm, gm)                                                       \
    asm volatile("cp.async.cg.shared.global [%0], [%1], 16;"                    \
                 :: "r"(sm), "l"(gm) : "memory")
#define CPCOMMIT()  asm volatile("cp.async.commit_group;" ::: "memory")
#define CPWAIT0()   asm volatile("cp.async.wait_group 0;" ::: "memory")

__device__ __forceinline__ uint32_t pack_h2(float a, float b) {
    __half2 t = __floats2half2_rn(a, b);        // x = low half
    return *reinterpret_cast<uint32_t*>(&t);
}
__device__ __forceinline__ int load_idx(const void* __restrict__ ei, int pos) {
    if (g_is64) return (int)((const long long*)ei)[pos];
    return ((const int*)ei)[pos];
}

// ---------------------------------------------------------------------------
// k1: dtype detect (block 0) + deg init
// ---------------------------------------------------------------------------
__global__ void k1_detect_initdeg(const unsigned int* __restrict__ w) {
    if (blockIdx.x == 0 && threadIdx.x == 0) {
        int is64 = 1;
        for (int i = 0; i < 128; i++)
            if (w[2 * i + 1] != 0u) { is64 = 0; break; }
        g_is64 = is64;
    }
    int i = blockIdx.x * blockDim.x + threadIdx.x;
    if (i < NN) g_deg[i] = 1.0f;
}

__global__ void k2_count_deg(const void* __restrict__ ei) {
    int e = blockIdx.x * blockDim.x + threadIdx.x;
    if (e < EE) atomicAdd(&g_deg[load_idx(ei, EE + e)], 1.0f);
}

// ---------------------------------------------------------------------------
// k3: calc_dis ([0,196)) + W1 cvt ([196,452)) + W2 cvt ([452,708))
//     Wh[n][k] = fp16(W[k][n])   (single fp16 term; A carries the error budget)
// ---------------------------------------------------------------------------
__global__ void k3_dis_wsplit(const float* __restrict__ W1,
                              const float* __restrict__ W2)
{
    int b = blockIdx.x;
    int tid = threadIdx.x;
    if (b < 196) {
        int i = b * 256 + tid;
        if (i < NN) g_dis[i] = rsqrtf(g_deg[i]);
        return;
    }
    int layer = (b < 452) ? 1 : 2;
    int t = (layer == 1) ? (b - 196) : (b - 452);
    const float* __restrict__ W = (layer == 1) ? W1 : W2;
    __half* __restrict__ Wh = (layer == 1) ? g_W1h : g_W2h;

    __shared__ float tt[32][33];
    int k0 = (t & 15) * 32, n0 = (t >> 4) * 32;
    int tx = tid & 31, ty = tid >> 5;
    for (int s = 0; s < 4; s++) {
        int j = ty + 8 * s;
        tt[j][tx] = W[(size_t)(k0 + j) * DD + n0 + tx];
    }
    __syncthreads();
    for (int s = 0; s < 4; s++) {
        int j = ty + 8 * s;
        Wh[(size_t)(n0 + j) * DD + k0 + tx] = __float2half_rn(tt[tx][j]);
    }
}

// ---------------------------------------------------------------------------
// fp16 GEMM: CTA 64x128, 8 warps (2m x 4n), warp tile 32x32, BK=64,
// 2 CTAs/SM, double-buffered smem + double-buffered ldmatrix fragments.
//   h = op(A)@W  with  D = Ah*Bh   (single fp16 each side, fp32 accum)
// Fused aggregation epilogue: HS = h*dis ; dest = h*dis^2 + bias
// ---------------------------------------------------------------------------
template <bool A_BUFB, bool RELU, int LAYER>
__global__ __launch_bounds__(256, 2) void gemm_f16(
    const float* __restrict__ Aext,
    const float* __restrict__ bias, float* __restrict__ dest_ext, int M)
{
    extern __shared__ __align__(16) char smem[];
    const float* __restrict__ A = A_BUFB ? (const float*)g_bufB : Aext;
    const __half* __restrict__ Wh = (LAYER == 1) ? g_W1h : g_W2h;
    float* __restrict__ dest = A_BUFB ? dest_ext : (float*)g_bufB;
    float* __restrict__ HS = g_bufA;

    const uint32_t sb = smem_u32(smem);
    const int tid = threadIdx.x, lane = tid & 31, wid = tid >> 5;
    const int wm = (wid & 1) * 32;       // 2 warps in m
    const int wn = (wid >> 1) * 32;      // 4 warps in n
    const int bm = blockIdx.y * BM;
    const int n0 = blockIdx.x * BN;

    // A loader: 64 rows x 64 floats = 1024 float4, 4/thread
    const int a_row = tid >> 4, a_c4 = tid & 15;         // +16 rows per r
    // B loader: 128 rows x 8 chunks16 = 1024, 4/thread
    const int b_row = tid >> 3, b_c = tid & 7;           // +32 rows per r

    float4 pa[4];

    auto issue_B = [&](int k0, int st) {
        uint32_t bh = sb + st * STAGE + ST_BH;
#pragma unroll
        for (int r = 0; r < 4; r++) {
            int row = b_row + 32 * r;
            size_t g = (size_t)(n0 + row) * DD + k0 + b_c * 8;
            uint32_t so = (uint32_t)(row * SA + b_c * 8) * 2;
            CPASYNC16(bh + so, (const void*)&Wh[g]);
        }
        CPCOMMIT();
    };
    auto issue_A = [&](int k0) {
#pragma unroll
        for (int r = 0; r < 4; r++) {
            int row = a_row + 16 * r;
            int g = bm + row;
            float4 v = make_float4(0.f, 0.f, 0.f, 0.f);
            if (g < M) v = *(const float4*)&A[(size_t)g * DD + k0 + a_c4 * 4];
            pa[r] = v;
        }
    };
    auto commit_A = [&](int st) {
        uint32_t ah = sb + st * STAGE;
#pragma unroll
        for (int r = 0; r < 4; r++) {
            int row = a_row + 16 * r;
            float4 v = pa[r];
            if (RELU) {
                v.x = fmaxf(v.x, 0.f); v.y = fmaxf(v.y, 0.f);
                v.z = fmaxf(v.z, 0.f); v.w = fmaxf(v.w, 0.f);
            }
            uint32_t so = (uint32_t)(row * SA + a_c4 * 4) * 2;
            asm volatile("st.shared.v2.b32 [%0], {%1,%2};" ::
                "r"(ah + so), "r"(pack_h2(v.x, v.y)), "r"(pack_h2(v.z, v.w))
                : "memory");
        }
    };

    // Fragment double buffers
    uint32_t ahf[2][2][4];                // [buf][mi][reg]
    uint32_t bhf[2][2][4];                // [buf][nj][reg]

    const uint32_t aoff0 = (uint32_t)(((wm + (lane & 15)) * SA
                          + 8 * (lane >> 4)) * 2);
    const uint32_t boff0 = (uint32_t)(((wn + (lane & 7) + 8 * (lane >> 4)) * SA
                          + 8 * ((lane >> 3) & 1)) * 2);

    auto load_frags = [&](int buf, uint32_t stBase, int k0s) {
        uint32_t aB = stBase + aoff0 + (uint32_t)(k0s * 2);
        uint32_t bB = stBase + ST_BH + boff0 + (uint32_t)(k0s * 2);
#pragma unroll
        for (int mi = 0; mi < 2; mi++)
            LDM4(ahf[buf][mi], aB + (uint32_t)(mi * 16 * SA * 2));
#pragma unroll
        for (int nj = 0; nj < 2; nj++)
            LDM4(bhf[buf][nj], bB + (uint32_t)(nj * 16 * SA * 2));
    };

    float c[2][4][4];
#pragma unroll
    for (int i = 0; i < 2; i++)
#pragma unroll
        for (int j = 0; j < 4; j++)
#pragma unroll
            for (int q = 0; q < 4; q++) c[i][j][q] = 0.0f;

    auto do_mma = [&](int buf) {
#pragma unroll
        for (int nj = 0; nj < 2; nj++)
#pragma unroll
            for (int mi = 0; mi < 2; mi++) {
                MMA(c[mi][nj * 2],     ahf[buf][mi], bhf[buf][nj][0], bhf[buf][nj][1]);
                MMA(c[mi][nj * 2 + 1], ahf[buf][mi], bhf[buf][nj][2], bhf[buf][nj][3]);
            }
    };

    // Prologue: fill stage 0
    issue_B(0, 0);
    issue_A(0);
    commit_A(0);
    CPWAIT0();
    __syncthreads();

    for (int it = 0; it < NIT; it++) {
        const int st = it & 1;
        const bool more = (it + 1 < NIT);
        if (more) {
            issue_B((it + 1) * BK, st ^ 1);
            issue_A((it + 1) * BK);
        }
        const uint32_t stBase = sb + st * STAGE;

        load_frags(0, stBase, 0);
#pragma unroll
        for (int ks = 0; ks < 4; ks++) {
            if (ks < 3) load_frags((ks + 1) & 1, stBase, (ks + 1) * 16);
            do_mma(ks & 1);
        }

        if (more) {
            commit_A(st ^ 1);
            CPWAIT0();
        }
        __syncthreads();
    }

    // Fused epilogue: hs = h*dis, dest = h*dis^2 + bias
#pragma unroll
    for (int mi = 0; mi < 2; mi++) {
        int r0 = bm + wm + mi * 16 + (lane >> 2);
        int r1 = r0 + 8;
        float d0 = (r0 < M) ? g_dis[r0] : 0.f;
        float d1 = (r1 < M) ? g_dis[r1] : 0.f;
#pragma unroll
        for (int nj2 = 0; nj2 < 4; nj2++) {
            int col = n0 + wn + nj2 * 8 + (lane & 3) * 2;
            float2 bv = *(const float2*)&bias[col];
            if (r0 < M) {
                float h0 = c[mi][nj2][0] * d0, h1 = c[mi][nj2][1] * d0;
                *(float2*)&HS[(size_t)r0 * DD + col] = make_float2(h0, h1);
                *(float2*)&dest[(size_t)r0 * DD + col] =
                    make_float2(fmaf(h0, d0, bv.x), fmaf(h1, d0, bv.y));
            }
            if (r1 < M) {
                float h0 = c[mi][nj2][2] * d1, h1 = c[mi][nj2][3] * d1;
                *(float2*)&HS[(size_t)r1 * DD + col] = make_float2(h0, h1);
                *(float2*)&dest[(size_t)r1 * DD + col] =
                    make_float2(fmaf(h0, d1, bv.x), fmaf(h1, d1, bv.y));
            }
        }
    }
}

// ---------------------------------------------------------------------------
// Edge scatter: agg[dst,:] += dis[dst] * hs[src,:]
// ---------------------------------------------------------------------------
template <bool TO_BUFB>
__global__ __launch_bounds__(256) void edge_scatter_kernel(
    const void* __restrict__ ei, float* __restrict__ agg_ext)
{
    float* __restrict__ agg = TO_BUFB ? (float*)g_bufB : agg_ext;
    const float* __restrict__ hs = g_bufA;
    int warp = (blockIdx.x * blockDim.x + threadIdx.x) >> 5;
    int lane = threadIdx.x & 31;
    if (warp >= EE) return;
    int s = load_idx(ei, warp);
    int d = load_idx(ei, EE + warp);
    float w = g_dis[d];
    const float4* hr = (const float4*)(hs + (size_t)s * DD);
    float* ar = agg + (size_t)d * DD;
#pragma unroll
    for (int i = 0; i < 4; i++) {
        int c4 = lane + i * 32;
        float4 v = hr[c4];
        float* p = ar + c4 * 4;
        asm volatile("red.global.add.v4.f32 [%0], {%1,%2,%3,%4};"
                     :: "l"(p), "f"(v.x * w), "f"(v.y * w),
                        "f"(v.z * w), "f"(v.w * w) : "memory");
    }
}

// ---------------------------------------------------------------------------
// >48KB dynamic smem opt-in (non-stream API: capture-safe; also at static init)
// ---------------------------------------------------------------------------
static void set_smem_attrs() {
    cudaFuncSetAttribute(gemm_f16<false, false, 1>,
                         cudaFuncAttributeMaxDynamicSharedMemorySize, SMEM_DYN);
    cudaFuncSetAttribute(gemm_f16<true, true, 2>,
                         cudaFuncAttributeMaxDynamicSharedMemorySize, SMEM_DYN);
}
namespace { struct GInit { GInit() { set_smem_attrs(); } } g_init; }

// ---------------------------------------------------------------------------
// Launch (graph-capturable; launch #4 = gemm1 for ncu's profiled slot)
// ---------------------------------------------------------------------------
extern "C" void kernel_launch(void* const* d_in, const int* in_sizes, int n_in,
                              void* d_out, int out_size)
{
    const float* x  = (const float*)d_in[0];
    const void*  ei = d_in[1];
    const float* W1 = (const float*)d_in[2];
    const float* b1 = (const float*)d_in[3];
    const float* W2 = (const float*)d_in[4];
    const float* b2 = (const float*)d_in[5];
    float* out = (float*)d_out;

    set_smem_attrs();

    dim3 gemm_grid(DD / BN, (NN + BM - 1) / BM);   // (4, 782); x-major: same-bm adjacent
    const int edge_blocks = (EE + 7) / 8;

    k1_detect_initdeg<<<196, 256>>>((const unsigned int*)ei);              // #1
    k2_count_deg<<<(EE + 255) / 256, 256>>>(ei);                           // #2
    k3_dis_wsplit<<<708, 256>>>(W1, W2);                                   // #3

    gemm_f16<false, false, 1><<<gemm_grid, 256, SMEM_DYN>>>(x, b1, nullptr, NN); // #4
    edge_scatter_kernel<true><<<edge_blocks, 256>>>(ei, nullptr);                // #5

    gemm_f16<true, true, 2><<<gemm_grid, 256, SMEM_DYN>>>(nullptr, b2, out, NN); // #6
    edge_scatter_kernel<false><<<edge_blocks, 256>>>(ei, out);                   // #7
}